// round 13
// baseline (speedup 1.0000x reference)
#include <cuda_runtime.h>
#include <cuda_bf16.h>
#include <cstdint>

#define NODES_MAX 100000
#define EDGES_MAX 1600000
#define HDIM 128
#define BN_EPS 1e-5f
#define SCAN_BLOCKS ((NODES_MAX + 1023) / 1024)   // 98
#define KS 136   // padded smem row stride in bf16 (272B = 16B-aligned, 4-bank shift/row)

// ---------------- scratch (static device globals; no allocation) ----------------
__device__ __align__(256) float g_bufA[(size_t)NODES_MAX * HDIM];            // hw (fp32)
__device__ __align__(256) __nv_bfloat16 g_actH[(size_t)NODES_MAX * HDIM];    // activation hi
__device__ __align__(256) __nv_bfloat16 g_actL[(size_t)NODES_MAX * HDIM];    // activation lo
__device__ __align__(256) __nv_bfloat16 g_w1H[HDIM * HDIM], g_w1L[HDIM * HDIM];  // W^T hi/lo
__device__ __align__(256) __nv_bfloat16 g_w2H[HDIM * HDIM], g_w2L[HDIM * HDIM];
__device__ __align__(256) __nv_bfloat16 g_cwH[HDIM * HDIM], g_cwL[HDIM * HDIM];
__device__ float g_dinv[NODES_MAX];
__device__ int   g_cnt[NODES_MAX];
__device__ int   g_incl[NODES_MAX];
__device__ int   g_blk[SCAN_BLOCKS];
__device__ int   g_rowptr[NODES_MAX + 1];
__device__ int   g_wpos[NODES_MAX];
__device__ int   g_eidx[EDGES_MAX];
__device__ float g_s1[HDIM], g_t1[HDIM], g_s2[HDIM], g_t2[HDIM];

// ---------------- degree / norm ----------------
__global__ void k_zero_cnt(int n) {
    int i = blockIdx.x * blockDim.x + threadIdx.x;
    if (i < n) g_cnt[i] = 0;
}

__global__ void k_count(const int* __restrict__ dst, int E) {
    int e = blockIdx.x * blockDim.x + threadIdx.x;
    if (e < E) atomicAdd(&g_cnt[dst[e]], 1);
}

__global__ void k_dinv(int n) {
    int i = blockIdx.x * blockDim.x + threadIdx.x;
    if (i < n) g_dinv[i] = rsqrtf((float)g_cnt[i] + 1.0f);  // +1 self loop
}

// ---------------- 3-pass parallel exclusive scan of degrees ----------------
__global__ __launch_bounds__(1024) void k_scan1(int n) {
    __shared__ int sh[1024];
    int t = threadIdx.x;
    int i = blockIdx.x * 1024 + t;
    int v = (i < n) ? g_cnt[i] : 0;
    sh[t] = v;
    __syncthreads();
    #pragma unroll
    for (int off = 1; off < 1024; off <<= 1) {
        int u = (t >= off) ? sh[t - off] : 0;
        __syncthreads();
        sh[t] += u;
        __syncthreads();
    }
    if (i < n) g_incl[i] = sh[t];
    if (t == 1023) g_blk[blockIdx.x] = sh[1023];
}

__global__ __launch_bounds__(128) void k_scan2(int nb, int n) {
    __shared__ int sh[128];
    int t = threadIdx.x;
    int v = (t < nb) ? g_blk[t] : 0;
    sh[t] = v;
    __syncthreads();
    #pragma unroll
    for (int off = 1; off < 128; off <<= 1) {
        int u = (t >= off) ? sh[t - off] : 0;
        __syncthreads();
        sh[t] += u;
        __syncthreads();
    }
    if (t < nb) g_blk[t] = sh[t] - v;
    if (t == nb - 1) g_rowptr[n] = sh[t];
}

__global__ __launch_bounds__(1024) void k_scan3(int n) {
    int i = blockIdx.x * 1024 + threadIdx.x;
    if (i < n) {
        int e = g_blk[blockIdx.x] + g_incl[i] - g_cnt[i];
        g_rowptr[i] = e;
        g_wpos[i] = e;
    }
}

// ---------------- CSR fill ----------------
__global__ void k_fill(const int* __restrict__ src, const int* __restrict__ dst, int E) {
    int e = blockIdx.x * blockDim.x + threadIdx.x;
    if (e < E) {
        int p = atomicAdd(&g_wpos[dst[e]], 1);
        g_eidx[p] = src[e];
    }
}

// ---------------- fold GCN bias + BN into per-channel scale/shift ----------------
__global__ void k_prep(const float* __restrict__ b1, const float* __restrict__ gg1,
                       const float* __restrict__ be1, const float* __restrict__ m1,
                       const float* __restrict__ v1,
                       const float* __restrict__ b2, const float* __restrict__ gg2,
                       const float* __restrict__ be2, const float* __restrict__ m2,
                       const float* __restrict__ v2) {
    int i = threadIdx.x;
    if (i < HDIM) {
        float s = gg1[i] * rsqrtf(v1[i] + BN_EPS);
        g_s1[i] = s;
        g_t1[i] = be1[i] + s * (b1[i] - m1[i]);
    } else {
        int j = i - HDIM;
        float s = gg2[j] * rsqrtf(v2[j] + BN_EPS);
        g_s2[j] = s;
        g_t2[j] = be2[j] + s * (b2[j] - m2[j]);
    }
}

// ---------------- one-time conversions ----------------
// x -> bf16 hi/lo (row-major, same layout)
__global__ void k_cvt(const float4* __restrict__ in,
                      __nv_bfloat162* __restrict__ oh, __nv_bfloat162* __restrict__ ol,
                      int n4) {
    int i = blockIdx.x * blockDim.x + threadIdx.x;
    if (i >= n4) return;
    float4 v = in[i];
    __nv_bfloat16 hx = __float2bfloat16(v.x), hy = __float2bfloat16(v.y);
    __nv_bfloat16 hz = __float2bfloat16(v.z), hw = __float2bfloat16(v.w);
    __nv_bfloat162 h01; h01.x = hx; h01.y = hy;
    __nv_bfloat162 h23; h23.x = hz; h23.y = hw;
    __nv_bfloat162 l01, l23;
    l01.x = __float2bfloat16(v.x - __bfloat162float(hx));
    l01.y = __float2bfloat16(v.y - __bfloat162float(hy));
    l23.x = __float2bfloat16(v.z - __bfloat162float(hz));
    l23.y = __float2bfloat16(v.w - __bfloat162float(hw));
    oh[i * 2] = h01; oh[i * 2 + 1] = h23;
    ol[i * 2] = l01; ol[i * 2 + 1] = l23;
}

// three W [k][n] fp32 -> W^T [n][k] bf16 hi/lo, one fused launch (192 blocks)
__global__ void k_cvtW3(const float* __restrict__ W1, const float* __restrict__ W2,
                        const float* __restrict__ W3,
                        __nv_bfloat16* __restrict__ o1H, __nv_bfloat16* __restrict__ o1L,
                        __nv_bfloat16* __restrict__ o2H, __nv_bfloat16* __restrict__ o2L,
                        __nv_bfloat16* __restrict__ o3H, __nv_bfloat16* __restrict__ o3L) {
    int which = blockIdx.x >> 6;                  // 64 blocks per matrix
    int i = (blockIdx.x & 63) * 256 + threadIdx.x;  // 0..16383
    const float* W = (which == 0) ? W1 : (which == 1) ? W2 : W3;
    __nv_bfloat16* oh = (which == 0) ? o1H : (which == 1) ? o2H : o3H;
    __nv_bfloat16* ol = (which == 0) ? o1L : (which == 1) ? o2L : o3L;
    int k = i >> 7, n = i & 127;
    float v = W[i];
    __nv_bfloat16 h = __float2bfloat16(v);
    oh[n * HDIM + k] = h;
    ol[n * HDIM + k] = __float2bfloat16(v - __bfloat162float(h));
}

// ---------------- tensor-core GEMM: out[M,128] = A[M,128] @ W[128,128] ----------------
// 256-row tiles, 512 threads (16 warps, 16 rows x 128 cols per warp).
// acc = Ah*Bh + Ah*Bl + Al*Bh (fp32 accumulate).
// mode 0: plain fp32 store.  mode 1: out[r] = relu(acc+bias).cW2 + cb2 (fused head).
#define MMA16816(d, a, bl, bh)                                              \
    asm volatile(                                                           \
        "mma.sync.aligned.m16n8k16.row.col.f32.bf16.bf16.f32 "              \
        "{%0,%1,%2,%3}, {%4,%5,%6,%7}, {%8,%9}, {%0,%1,%2,%3};"             \
        : "+f"(d[0]), "+f"(d[1]), "+f"(d[2]), "+f"(d[3])                    \
        : "r"(a[0]), "r"(a[1]), "r"(a[2]), "r"(a[3]), "r"(bl), "r"(bh))

__global__ __launch_bounds__(512) void k_mma256(
    const __nv_bfloat16* __restrict__ AH, const __nv_bfloat16* __restrict__ AL,
    const __nv_bfloat16* __restrict__ WH, const __nv_bfloat16* __restrict__ WL,
    float* __restrict__ out, const float* __restrict__ bias,
    const float* __restrict__ cw2, const float* __restrict__ cb2,
    int M, int mode)
{
    extern __shared__ __align__(16) char smraw[];
    __nv_bfloat16* A0 = (__nv_bfloat16*)smraw;          // A hi  [256][KS]
    __nv_bfloat16* A1 = A0 + 256 * KS;                  // A lo
    __nv_bfloat16* B0 = A1 + 256 * KS;                  // W^T hi [128][KS]
    __nv_bfloat16* B1 = B0 + 128 * KS;                  // W^T lo

    int tid = threadIdx.x;
    int m0 = blockIdx.x * 256;

    // ---- stage A (pure copy): 2 threads per row, 64 k (8 float4) each ----
    {
        int r = tid >> 1, kh = (tid & 1) * 64;
        int m = m0 + r;
        float4* d0 = (float4*)(A0 + r * KS + kh);
        float4* d1 = (float4*)(A1 + r * KS + kh);
        if (m < M) {
            const float4* s0 = (const float4*)(AH + (size_t)m * HDIM + kh);
            const float4* s1 = (const float4*)(AL + (size_t)m * HDIM + kh);
            #pragma unroll
            for (int i = 0; i < 8; i++) { d0[i] = s0[i]; d1[i] = s1[i]; }
        } else {
            float4 z = {0.f, 0.f, 0.f, 0.f};
            #pragma unroll
            for (int i = 0; i < 8; i++) { d0[i] = z; d1[i] = z; }
        }
    }
    // ---- stage W^T (pure copy): 2048 float4 per buffer, 512 threads ----
    #pragma unroll
    for (int i = tid; i < 2048; i += 512) {
        int n = i >> 4, kc = i & 15;
        *(float4*)(B0 + n * KS + kc * 8) = ((const float4*)WH)[i];
        *(float4*)(B1 + n * KS + kc * 8) = ((const float4*)WL)[i];
    }
    __syncthreads();

    int lane = tid & 31, warp = tid >> 5;      // 16 warps
    int gid = lane >> 2, tig = lane & 3;
    int rbase = warp * 16 + gid;               // local row for c0/c1; +8 for c2/c3

    float acc[16][4];
    #pragma unroll
    for (int nt = 0; nt < 16; nt++)
        #pragma unroll
        for (int j = 0; j < 4; j++) acc[nt][j] = 0.f;

    const __nv_bfloat16* a0r = A0 + rbase * KS + tig * 2;
    const __nv_bfloat16* a1r = A1 + rbase * KS + tig * 2;

    #pragma unroll
    for (int ks = 0; ks < 128; ks += 16) {
        uint32_t ah[4], al[4];
        ah[0] = *(const uint32_t*)(a0r + ks);
        ah[1] = *(const uint32_t*)(a0r + 8 * KS + ks);
        ah[2] = *(const uint32_t*)(a0r + ks + 8);
        ah[3] = *(const uint32_t*)(a0r + 8 * KS + ks + 8);
        al[0] = *(const uint32_t*)(a1r + ks);
        al[1] = *(const uint32_t*)(a1r + 8 * KS + ks);
        al[2] = *(const uint32_t*)(a1r + ks + 8);
        al[3] = *(const uint32_t*)(a1r + 8 * KS + ks + 8);
        #pragma unroll
        for (int nt = 0; nt < 16; nt++) {
            int col = nt * 8 + gid;
            const __nv_bfloat16* bh = B0 + col * KS + tig * 2;
            const __nv_bfloat16* bl = B1 + col * KS + tig * 2;
            uint32_t bh0 = *(const uint32_t*)(bh + ks);
            uint32_t bh1 = *(const uint32_t*)(bh + ks + 8);
            uint32_t bl0 = *(const uint32_t*)(bl + ks);
            uint32_t bl1 = *(const uint32_t*)(bl + ks + 8);
            MMA16816(acc[nt], ah, bh0, bh1);
            MMA16816(acc[nt], ah, bl0, bl1);
            MMA16816(acc[nt], al, bh0, bh1);
        }
    }

    int r1 = m0 + rbase, r2 = r1 + 8;
    if (mode == 0) {
        #pragma unroll
        for (int nt = 0; nt < 16; nt++) {
            int c = nt * 8 + tig * 2;
            if (r1 < M) {
                float2 v = {acc[nt][0], acc[nt][1]};
                *(float2*)(out + (size_t)r1 * HDIM + c) = v;
            }
            if (r2 < M) {
                float2 v = {acc[nt][2], acc[nt][3]};
                *(float2*)(out + (size_t)r2 * HDIM + c) = v;
            }
        }
    } else {
        float p1 = 0.f, p2 = 0.f;
        #pragma unroll
        for (int nt = 0; nt < 16; nt++) {
            int c = nt * 8 + tig * 2;
            float b0 = bias[c], b1v = bias[c + 1];
            float w0 = cw2[c], w1 = cw2[c + 1];
            p1 = fmaf(fmaxf(acc[nt][0] + b0, 0.f), w0, p1);
            p1 = fmaf(fmaxf(acc[nt][1] + b1v, 0.f), w1, p1);
            p2 = fmaf(fmaxf(acc[nt][2] + b0, 0.f), w0, p2);
            p2 = fmaf(fmaxf(acc[nt][3] + b1v, 0.f), w1, p2);
        }
        p1 += __shfl_xor_sync(0xFFFFFFFFu, p1, 1);
        p1 += __shfl_xor_sync(0xFFFFFFFFu, p1, 2);
        p2 += __shfl_xor_sync(0xFFFFFFFFu, p2, 1);
        p2 += __shfl_xor_sync(0xFFFFFFFFu, p2, 2);
        if (tig == 0) {
            float cb = cb2[0];
            if (r1 < M) out[r1] = p1 + cb;
            if (r2 < M) out[r2] = p2 + cb;
        }
    }
}

// ---------------- CSR gather + self-loop + BN + ReLU -> bf16 hi/lo ----------------
__global__ __launch_bounds__(256) void k_gather_bn(
    const float4* __restrict__ hw,
    __nv_bfloat162* __restrict__ outH, __nv_bfloat162* __restrict__ outL,
    const float* __restrict__ sc, const float* __restrict__ tc, int n)
{
    int node = (blockIdx.x * blockDim.x + threadIdx.x) >> 5;
    if (node >= n) return;
    int lane = threadIdx.x & 31;

    int beg = g_rowptr[node];
    int end = g_rowptr[node + 1];
    float dd = g_dinv[node];

    float4 v = hw[(size_t)node * 32 + lane];
    float4 acc = {v.x * dd, v.y * dd, v.z * dd, v.w * dd};   // self loop

    int j = beg;
    for (; j + 1 < end; j += 2) {
        int s0 = g_eidx[j], s1 = g_eidx[j + 1];
        float w0 = g_dinv[s0], w1 = g_dinv[s1];
        float4 h0 = hw[(size_t)s0 * 32 + lane];
        float4 h1 = hw[(size_t)s1 * 32 + lane];
        acc.x = fmaf(h0.x, w0, acc.x); acc.y = fmaf(h0.y, w0, acc.y);
        acc.z = fmaf(h0.z, w0, acc.z); acc.w = fmaf(h0.w, w0, acc.w);
        acc.x = fmaf(h1.x, w1, acc.x); acc.y = fmaf(h1.y, w1, acc.y);
        acc.z = fmaf(h1.z, w1, acc.z); acc.w = fmaf(h1.w, w1, acc.w);
    }
    if (j < end) {
        int s0 = g_eidx[j];
        float w0 = g_dinv[s0];
        float4 h0 = hw[(size_t)s0 * 32 + lane];
        acc.x = fmaf(h0.x, w0, acc.x); acc.y = fmaf(h0.y, w0, acc.y);
        acc.z = fmaf(h0.z, w0, acc.z); acc.w = fmaf(h0.w, w0, acc.w);
    }

    int c = lane << 2;
    float rx = fmaxf(fmaf(acc.x * dd, sc[c + 0], tc[c + 0]), 0.f);
    float ry = fmaxf(fmaf(acc.y * dd, sc[c + 1], tc[c + 1]), 0.f);
    float rz = fmaxf(fmaf(acc.z * dd, sc[c + 2], tc[c + 2]), 0.f);
    float rw = fmaxf(fmaf(acc.w * dd, sc[c + 3], tc[c + 3]), 0.f);

    __nv_bfloat16 hx = __float2bfloat16(rx), hy = __float2bfloat16(ry);
    __nv_bfloat16 hz = __float2bfloat16(rz), hw2 = __float2bfloat16(rw);
    __nv_bfloat162 h01; h01.x = hx; h01.y = hy;
    __nv_bfloat162 h23; h23.x = hz; h23.y = hw2;
    __nv_bfloat162 l01, l23;
    l01.x = __float2bfloat16(rx - __bfloat162float(hx));
    l01.y = __float2bfloat16(ry - __bfloat162float(hy));
    l23.x = __float2bfloat16(rz - __bfloat162float(hz));
    l23.y = __float2bfloat16(rw - __bfloat162float(hw2));

    size_t o = (size_t)node * 64 + lane * 2;
    outH[o] = h01; outH[o + 1] = h23;
    outL[o] = l01; outL[o + 1] = l23;
}

// ---------------- host orchestration ----------------
extern "C" void kernel_launch(void* const* d_in, const int* in_sizes, int n_in,
                              void* d_out, int out_size) {
    const float* x   = (const float*)d_in[0];
    const int*   ei  = (const int*)d_in[1];       // JAX x64-disabled: int32
    const float* W1  = (const float*)d_in[2];
    const float* b1  = (const float*)d_in[3];
    const float* gg1 = (const float*)d_in[4];
    const float* be1 = (const float*)d_in[5];
    const float* m1  = (const float*)d_in[6];
    const float* v1  = (const float*)d_in[7];
    const float* W2  = (const float*)d_in[8];
    const float* b2  = (const float*)d_in[9];
    const float* gg2 = (const float*)d_in[10];
    const float* be2 = (const float*)d_in[11];
    const float* m2  = (const float*)d_in[12];
    const float* v2  = (const float*)d_in[13];
    const float* cW1 = (const float*)d_in[14];
    const float* cb1 = (const float*)d_in[15];
    const float* cW2 = (const float*)d_in[16];
    const float* cb2 = (const float*)d_in[17];
    float* out = (float*)d_out;

    int M = in_sizes[0] / HDIM;     // 100000
    int E = in_sizes[1] / 2;        // 1600000
    const int* src = ei;
    const int* dst = ei + E;

    void *pA, *pAH, *pAL, *pW1H, *pW1L, *pW2H, *pW2L, *pCWH, *pCWL;
    void *ps1, *pt1, *ps2, *pt2;
    cudaGetSymbolAddress(&pA, g_bufA);
    cudaGetSymbolAddress(&pAH, g_actH);
    cudaGetSymbolAddress(&pAL, g_actL);
    cudaGetSymbolAddress(&pW1H, g_w1H);  cudaGetSymbolAddress(&pW1L, g_w1L);
    cudaGetSymbolAddress(&pW2H, g_w2H);  cudaGetSymbolAddress(&pW2L, g_w2L);
    cudaGetSymbolAddress(&pCWH, g_cwH);  cudaGetSymbolAddress(&pCWL, g_cwL);
    cudaGetSymbolAddress(&ps1, g_s1);
    cudaGetSymbolAddress(&pt1, g_t1);
    cudaGetSymbolAddress(&ps2, g_s2);
    cudaGetSymbolAddress(&pt2, g_t2);
    float* bufA = (float*)pA;
    __nv_bfloat16* actH = (__nv_bfloat16*)pAH;
    __nv_bfloat16* actL = (__nv_bfloat16*)pAL;

    const int SMEM = (2 * 256 + 2 * 128) * KS * (int)sizeof(__nv_bfloat16);  // 208896 B
    cudaFuncSetAttribute(k_mma256, cudaFuncAttributeMaxDynamicSharedMemorySize, SMEM);

    int nThreads = 256;
    int gNodes   = (M + nThreads - 1) / nThreads;
    int gEdges   = (E + nThreads - 1) / nThreads;
    int gGemm    = (M + 255) / 256;
    int gWarp    = (M + 7) / 8;
    int gScan    = (M + 1023) / 1024;
    int n4       = M * (HDIM / 4);
    int gCvt     = (n4 + nThreads - 1) / nThreads;

    // one-time conversions
    k_cvt<<<gCvt, nThreads>>>((const float4*)x, (__nv_bfloat162*)actH,
                              (__nv_bfloat162*)actL, n4);
    k_cvtW3<<<192, 256>>>(W1, W2, cW1,
                          (__nv_bfloat16*)pW1H, (__nv_bfloat16*)pW1L,
                          (__nv_bfloat16*)pW2H, (__nv_bfloat16*)pW2L,
                          (__nv_bfloat16*)pCWH, (__nv_bfloat16*)pCWL);

    // degree / CSR / normalization (built once, reused for both layers)
    k_zero_cnt<<<gNodes, nThreads>>>(M);
    k_count<<<gEdges, nThreads>>>(dst, E);
    k_dinv<<<gNodes, nThreads>>>(M);
    k_scan1<<<gScan, 1024>>>(M);
    k_scan2<<<1, 128>>>(gScan, M);
    k_scan3<<<gScan, 1024>>>(M);
    k_fill<<<gEdges, nThreads>>>(src, dst, E);
    k_prep<<<1, 256>>>(b1, gg1, be1, m1, v1, b2, gg2, be2, m2, v2);

    // layer 1: hw = x@W1 -> bufA; gather+BN+ReLU -> act hi/lo
    k_mma256<<<gGemm, 512, SMEM>>>(actH, actL, (__nv_bfloat16*)pW1H, (__nv_bfloat16*)pW1L,
                                   bufA, nullptr, nullptr, nullptr, M, 0);
    k_gather_bn<<<gWarp, 256>>>((const float4*)bufA, (__nv_bfloat162*)actH,
                                (__nv_bfloat162*)actL,
                                (const float*)ps1, (const float*)pt1, M);

    // layer 2
    k_mma256<<<gGemm, 512, SMEM>>>(actH, actL, (__nv_bfloat16*)pW2H, (__nv_bfloat16*)pW2L,
                                   bufA, nullptr, nullptr, nullptr, M, 0);
    k_gather_bn<<<gWarp, 256>>>((const float4*)bufA, (__nv_bfloat162*)actH,
                                (__nv_bfloat162*)actL,
                                (const float*)ps2, (const float*)pt2, M);

    // classifier fully fused: out = relu(act@cW1 + cb1) @ cW2 + cb2
    k_mma256<<<gGemm, 512, SMEM>>>(actH, actL, (__nv_bfloat16*)pCWH, (__nv_bfloat16*)pCWL,
                                   out, cb1, cW2, cb2, M, 1);
}

// round 14
// speedup vs baseline: 1.0516x; 1.0516x over previous
#include <cuda_runtime.h>
#include <cuda_bf16.h>
#include <cstdint>

#define NODES_MAX 100000
#define EDGES_MAX 1600000
#define HDIM 128
#define BN_EPS 1e-5f
#define SCAN_BLOCKS ((NODES_MAX + 1023) / 1024)   // 98
#define KS 136   // padded smem row stride in bf16 (272B = 16B-aligned, 4-bank shift/row)

// ---------------- scratch (static device globals; no allocation) ----------------
__device__ __align__(256) float g_bufA[(size_t)NODES_MAX * HDIM];            // hw (fp32)
__device__ __align__(256) __nv_bfloat16 g_actH[(size_t)NODES_MAX * HDIM];    // activation hi
__device__ __align__(256) __nv_bfloat16 g_actL[(size_t)NODES_MAX * HDIM];    // activation lo
__device__ __align__(256) __nv_bfloat16 g_w1H[HDIM * HDIM], g_w1L[HDIM * HDIM];  // W^T hi/lo
__device__ __align__(256) __nv_bfloat16 g_w2H[HDIM * HDIM], g_w2L[HDIM * HDIM];
__device__ __align__(256) __nv_bfloat16 g_cwH[HDIM * HDIM], g_cwL[HDIM * HDIM];
__device__ float g_dinv[NODES_MAX];
__device__ int   g_cnt[NODES_MAX];
__device__ int   g_incl[NODES_MAX];
__device__ int   g_blk[SCAN_BLOCKS];
__device__ int   g_rowptr[NODES_MAX + 1];
__device__ int   g_wpos[NODES_MAX];
__device__ int   g_eidx[EDGES_MAX];
__device__ float g_s1[HDIM], g_t1[HDIM], g_s2[HDIM], g_t2[HDIM];

// ---------------- degree / norm ----------------
__global__ void k_zero_cnt(int n) {
    int i = blockIdx.x * blockDim.x + threadIdx.x;
    if (i < n) g_cnt[i] = 0;
}

__global__ void k_count(const int* __restrict__ dst, int E) {
    int e = blockIdx.x * blockDim.x + threadIdx.x;
    if (e < E) atomicAdd(&g_cnt[dst[e]], 1);
}

__global__ void k_dinv(int n) {
    int i = blockIdx.x * blockDim.x + threadIdx.x;
    if (i < n) g_dinv[i] = rsqrtf((float)g_cnt[i] + 1.0f);  // +1 self loop
}

// ---------------- 3-pass parallel exclusive scan of degrees ----------------
__global__ __launch_bounds__(1024) void k_scan1(int n) {
    __shared__ int sh[1024];
    int t = threadIdx.x;
    int i = blockIdx.x * 1024 + t;
    int v = (i < n) ? g_cnt[i] : 0;
    sh[t] = v;
    __syncthreads();
    #pragma unroll
    for (int off = 1; off < 1024; off <<= 1) {
        int u = (t >= off) ? sh[t - off] : 0;
        __syncthreads();
        sh[t] += u;
        __syncthreads();
    }
    if (i < n) g_incl[i] = sh[t];
    if (t == 1023) g_blk[blockIdx.x] = sh[1023];
}

__global__ __launch_bounds__(128) void k_scan2(int nb, int n) {
    __shared__ int sh[128];
    int t = threadIdx.x;
    int v = (t < nb) ? g_blk[t] : 0;
    sh[t] = v;
    __syncthreads();
    #pragma unroll
    for (int off = 1; off < 128; off <<= 1) {
        int u = (t >= off) ? sh[t - off] : 0;
        __syncthreads();
        sh[t] += u;
        __syncthreads();
    }
    if (t < nb) g_blk[t] = sh[t] - v;
    if (t == nb - 1) g_rowptr[n] = sh[t];
}

__global__ __launch_bounds__(1024) void k_scan3(int n) {
    int i = blockIdx.x * 1024 + threadIdx.x;
    if (i < n) {
        int e = g_blk[blockIdx.x] + g_incl[i] - g_cnt[i];
        g_rowptr[i] = e;
        g_wpos[i] = e;
    }
}

// ---------------- CSR fill ----------------
__global__ void k_fill(const int* __restrict__ src, const int* __restrict__ dst, int E) {
    int e = blockIdx.x * blockDim.x + threadIdx.x;
    if (e < E) {
        int p = atomicAdd(&g_wpos[dst[e]], 1);
        g_eidx[p] = src[e];
    }
}

// ---------------- fold GCN bias + BN into per-channel scale/shift ----------------
__global__ void k_prep(const float* __restrict__ b1, const float* __restrict__ gg1,
                       const float* __restrict__ be1, const float* __restrict__ m1,
                       const float* __restrict__ v1,
                       const float* __restrict__ b2, const float* __restrict__ gg2,
                       const float* __restrict__ be2, const float* __restrict__ m2,
                       const float* __restrict__ v2) {
    int i = threadIdx.x;
    if (i < HDIM) {
        float s = gg1[i] * rsqrtf(v1[i] + BN_EPS);
        g_s1[i] = s;
        g_t1[i] = be1[i] + s * (b1[i] - m1[i]);
    } else {
        int j = i - HDIM;
        float s = gg2[j] * rsqrtf(v2[j] + BN_EPS);
        g_s2[j] = s;
        g_t2[j] = be2[j] + s * (b2[j] - m2[j]);
    }
}

// ---------------- one-time conversions ----------------
// x -> bf16 hi/lo (row-major, same layout)
__global__ void k_cvt(const float4* __restrict__ in,
                      __nv_bfloat162* __restrict__ oh, __nv_bfloat162* __restrict__ ol,
                      int n4) {
    int i = blockIdx.x * blockDim.x + threadIdx.x;
    if (i >= n4) return;
    float4 v = in[i];
    __nv_bfloat16 hx = __float2bfloat16(v.x), hy = __float2bfloat16(v.y);
    __nv_bfloat16 hz = __float2bfloat16(v.z), hw = __float2bfloat16(v.w);
    __nv_bfloat162 h01; h01.x = hx; h01.y = hy;
    __nv_bfloat162 h23; h23.x = hz; h23.y = hw;
    __nv_bfloat162 l01, l23;
    l01.x = __float2bfloat16(v.x - __bfloat162float(hx));
    l01.y = __float2bfloat16(v.y - __bfloat162float(hy));
    l23.x = __float2bfloat16(v.z - __bfloat162float(hz));
    l23.y = __float2bfloat16(v.w - __bfloat162float(hw));
    oh[i * 2] = h01; oh[i * 2 + 1] = h23;
    ol[i * 2] = l01; ol[i * 2 + 1] = l23;
}

// three W [k][n] fp32 -> W^T [n][k] bf16 hi/lo, one fused launch (192 blocks)
__global__ void k_cvtW3(const float* __restrict__ W1, const float* __restrict__ W2,
                        const float* __restrict__ W3,
                        __nv_bfloat16* __restrict__ o1H, __nv_bfloat16* __restrict__ o1L,
                        __nv_bfloat16* __restrict__ o2H, __nv_bfloat16* __restrict__ o2L,
                        __nv_bfloat16* __restrict__ o3H, __nv_bfloat16* __restrict__ o3L) {
    int which = blockIdx.x >> 6;                  // 64 blocks per matrix
    int i = (blockIdx.x & 63) * 256 + threadIdx.x;  // 0..16383
    const float* W = (which == 0) ? W1 : (which == 1) ? W2 : W3;
    __nv_bfloat16* oh = (which == 0) ? o1H : (which == 1) ? o2H : o3H;
    __nv_bfloat16* ol = (which == 0) ? o1L : (which == 1) ? o2L : o3L;
    int k = i >> 7, n = i & 127;
    float v = W[i];
    __nv_bfloat16 h = __float2bfloat16(v);
    oh[n * HDIM + k] = h;
    ol[n * HDIM + k] = __float2bfloat16(v - __bfloat162float(h));
}

// ---------------- tensor-core GEMM: out[M,128] = A[M,128] @ W[128,128] ----------------
// 128-row tiles, 256 threads (8 warps, 16 rows x 128 cols per warp). (R10 proven config)
// acc = Ah*Bh + Ah*Bl + Al*Bh (fp32 accumulate).
// mode 0: plain fp32 store.  mode 1: out[r] = relu(acc+bias).cW2 + cb2 (fused head).
#define MMA16816(d, a, bl, bh)                                              \
    asm volatile(                                                           \
        "mma.sync.aligned.m16n8k16.row.col.f32.bf16.bf16.f32 "              \
        "{%0,%1,%2,%3}, {%4,%5,%6,%7}, {%8,%9}, {%0,%1,%2,%3};"             \
        : "+f"(d[0]), "+f"(d[1]), "+f"(d[2]), "+f"(d[3])                    \
        : "r"(a[0]), "r"(a[1]), "r"(a[2]), "r"(a[3]), "r"(bl), "r"(bh))

__global__ __launch_bounds__(256) void k_mma128(
    const __nv_bfloat16* __restrict__ AH, const __nv_bfloat16* __restrict__ AL,
    const __nv_bfloat16* __restrict__ WH, const __nv_bfloat16* __restrict__ WL,
    float* __restrict__ out, const float* __restrict__ bias,
    const float* __restrict__ cw2, const float* __restrict__ cb2,
    int M, int mode)
{
    extern __shared__ __align__(16) char smraw[];
    __nv_bfloat16* A0 = (__nv_bfloat16*)smraw;          // A hi  [128][KS]
    __nv_bfloat16* A1 = A0 + 128 * KS;                  // A lo
    __nv_bfloat16* B0 = A1 + 128 * KS;                  // W^T hi [n][KS]
    __nv_bfloat16* B1 = B0 + 128 * KS;                  // W^T lo

    int tid = threadIdx.x;
    int m0 = blockIdx.x * 128;

    // ---- stage A (pure copy): 2 threads per row, 64 k (128B = 8 float4) each ----
    {
        int r = tid >> 1, kh = (tid & 1) * 64;
        int m = m0 + r;
        float4* d0 = (float4*)(A0 + r * KS + kh);
        float4* d1 = (float4*)(A1 + r * KS + kh);
        if (m < M) {
            const float4* s0 = (const float4*)(AH + (size_t)m * HDIM + kh);
            const float4* s1 = (const float4*)(AL + (size_t)m * HDIM + kh);
            #pragma unroll
            for (int i = 0; i < 8; i++) { d0[i] = s0[i]; d1[i] = s1[i]; }
        } else {
            float4 z = {0.f, 0.f, 0.f, 0.f};
            #pragma unroll
            for (int i = 0; i < 8; i++) { d0[i] = z; d1[i] = z; }
        }
    }
    // ---- stage W^T (pure copy): 2048 float4 per buffer ----
    #pragma unroll
    for (int i = tid; i < 2048; i += 256) {
        int n = i >> 4, kc = i & 15;
        *(float4*)(B0 + n * KS + kc * 8) = ((const float4*)WH)[i];
        *(float4*)(B1 + n * KS + kc * 8) = ((const float4*)WL)[i];
    }
    __syncthreads();

    int lane = tid & 31, warp = tid >> 5;
    int gid = lane >> 2, tig = lane & 3;
    int rbase = warp * 16 + gid;            // local row for c0/c1; +8 for c2/c3

    float acc[16][4];
    #pragma unroll
    for (int nt = 0; nt < 16; nt++)
        #pragma unroll
        for (int j = 0; j < 4; j++) acc[nt][j] = 0.f;

    const __nv_bfloat16* a0r = A0 + rbase * KS + tig * 2;
    const __nv_bfloat16* a1r = A1 + rbase * KS + tig * 2;

    #pragma unroll
    for (int ks = 0; ks < 128; ks += 16) {
        uint32_t ah[4], al[4];
        ah[0] = *(const uint32_t*)(a0r + ks);
        ah[1] = *(const uint32_t*)(a0r + 8 * KS + ks);
        ah[2] = *(const uint32_t*)(a0r + ks + 8);
        ah[3] = *(const uint32_t*)(a0r + 8 * KS + ks + 8);
        al[0] = *(const uint32_t*)(a1r + ks);
        al[1] = *(const uint32_t*)(a1r + 8 * KS + ks);
        al[2] = *(const uint32_t*)(a1r + ks + 8);
        al[3] = *(const uint32_t*)(a1r + 8 * KS + ks + 8);
        #pragma unroll
        for (int nt = 0; nt < 16; nt++) {
            int col = nt * 8 + gid;
            const __nv_bfloat16* bh = B0 + col * KS + tig * 2;
            const __nv_bfloat16* bl = B1 + col * KS + tig * 2;
            uint32_t bh0 = *(const uint32_t*)(bh + ks);
            uint32_t bh1 = *(const uint32_t*)(bh + ks + 8);
            uint32_t bl0 = *(const uint32_t*)(bl + ks);
            uint32_t bl1 = *(const uint32_t*)(bl + ks + 8);
            MMA16816(acc[nt], ah, bh0, bh1);
            MMA16816(acc[nt], ah, bl0, bl1);
            MMA16816(acc[nt], al, bh0, bh1);
        }
    }

    int r1 = m0 + rbase, r2 = r1 + 8;
    if (mode == 0) {
        #pragma unroll
        for (int nt = 0; nt < 16; nt++) {
            int c = nt * 8 + tig * 2;
            if (r1 < M) {
                float2 v = {acc[nt][0], acc[nt][1]};
                *(float2*)(out + (size_t)r1 * HDIM + c) = v;
            }
            if (r2 < M) {
                float2 v = {acc[nt][2], acc[nt][3]};
                *(float2*)(out + (size_t)r2 * HDIM + c) = v;
            }
        }
    } else {
        float p1 = 0.f, p2 = 0.f;
        #pragma unroll
        for (int nt = 0; nt < 16; nt++) {
            int c = nt * 8 + tig * 2;
            float b0 = bias[c], b1v = bias[c + 1];
            float w0 = cw2[c], w1 = cw2[c + 1];
            p1 = fmaf(fmaxf(acc[nt][0] + b0, 0.f), w0, p1);
            p1 = fmaf(fmaxf(acc[nt][1] + b1v, 0.f), w1, p1);
            p2 = fmaf(fmaxf(acc[nt][2] + b0, 0.f), w0, p2);
            p2 = fmaf(fmaxf(acc[nt][3] + b1v, 0.f), w1, p2);
        }
        p1 += __shfl_xor_sync(0xFFFFFFFFu, p1, 1);
        p1 += __shfl_xor_sync(0xFFFFFFFFu, p1, 2);
        p2 += __shfl_xor_sync(0xFFFFFFFFu, p2, 1);
        p2 += __shfl_xor_sync(0xFFFFFFFFu, p2, 2);
        if (tig == 0) {
            float cb = cb2[0];
            if (r1 < M) out[r1] = p1 + cb;
            if (r2 < M) out[r2] = p2 + cb;
        }
    }
}

// ---------------- CSR gather + self-loop + BN + ReLU -> bf16 hi/lo ----------------
__global__ __launch_bounds__(256) void k_gather_bn(
    const float4* __restrict__ hw,
    __nv_bfloat162* __restrict__ outH, __nv_bfloat162* __restrict__ outL,
    const float* __restrict__ sc, const float* __restrict__ tc, int n)
{
    int node = (blockIdx.x * blockDim.x + threadIdx.x) >> 5;
    if (node >= n) return;
    int lane = threadIdx.x & 31;

    int beg = g_rowptr[node];
    int end = g_rowptr[node + 1];
    float dd = g_dinv[node];

    float4 v = hw[(size_t)node * 32 + lane];
    float4 acc = {v.x * dd, v.y * dd, v.z * dd, v.w * dd};   // self loop

    int j = beg;
    for (; j + 1 < end; j += 2) {
        int s0 = g_eidx[j], s1 = g_eidx[j + 1];
        float w0 = g_dinv[s0], w1 = g_dinv[s1];
        float4 h0 = hw[(size_t)s0 * 32 + lane];
        float4 h1 = hw[(size_t)s1 * 32 + lane];
        acc.x = fmaf(h0.x, w0, acc.x); acc.y = fmaf(h0.y, w0, acc.y);
        acc.z = fmaf(h0.z, w0, acc.z); acc.w = fmaf(h0.w, w0, acc.w);
        acc.x = fmaf(h1.x, w1, acc.x); acc.y = fmaf(h1.y, w1, acc.y);
        acc.z = fmaf(h1.z, w1, acc.z); acc.w = fmaf(h1.w, w1, acc.w);
    }
    if (j < end) {
        int s0 = g_eidx[j];
        float w0 = g_dinv[s0];
        float4 h0 = hw[(size_t)s0 * 32 + lane];
        acc.x = fmaf(h0.x, w0, acc.x); acc.y = fmaf(h0.y, w0, acc.y);
        acc.z = fmaf(h0.z, w0, acc.z); acc.w = fmaf(h0.w, w0, acc.w);
    }

    int c = lane << 2;
    float rx = fmaxf(fmaf(acc.x * dd, sc[c + 0], tc[c + 0]), 0.f);
    float ry = fmaxf(fmaf(acc.y * dd, sc[c + 1], tc[c + 1]), 0.f);
    float rz = fmaxf(fmaf(acc.z * dd, sc[c + 2], tc[c + 2]), 0.f);
    float rw = fmaxf(fmaf(acc.w * dd, sc[c + 3], tc[c + 3]), 0.f);

    __nv_bfloat16 hx = __float2bfloat16(rx), hy = __float2bfloat16(ry);
    __nv_bfloat16 hz = __float2bfloat16(rz), hw2 = __float2bfloat16(rw);
    __nv_bfloat162 h01; h01.x = hx; h01.y = hy;
    __nv_bfloat162 h23; h23.x = hz; h23.y = hw2;
    __nv_bfloat162 l01, l23;
    l01.x = __float2bfloat16(rx - __bfloat162float(hx));
    l01.y = __float2bfloat16(ry - __bfloat162float(hy));
    l23.x = __float2bfloat16(rz - __bfloat162float(hz));
    l23.y = __float2bfloat16(rw - __bfloat162float(hw2));

    size_t o = (size_t)node * 64 + lane * 2;
    outH[o] = h01; outH[o + 1] = h23;
    outL[o] = l01; outL[o + 1] = l23;
}

// ---------------- host orchestration ----------------
extern "C" void kernel_launch(void* const* d_in, const int* in_sizes, int n_in,
                              void* d_out, int out_size) {
    const float* x   = (const float*)d_in[0];
    const int*   ei  = (const int*)d_in[1];       // JAX x64-disabled: int32
    const float* W1  = (const float*)d_in[2];
    const float* b1  = (const float*)d_in[3];
    const float* gg1 = (const float*)d_in[4];
    const float* be1 = (const float*)d_in[5];
    const float* m1  = (const float*)d_in[6];
    const float* v1  = (const float*)d_in[7];
    const float* W2  = (const float*)d_in[8];
    const float* b2  = (const float*)d_in[9];
    const float* gg2 = (const float*)d_in[10];
    const float* be2 = (const float*)d_in[11];
    const float* m2  = (const float*)d_in[12];
    const float* v2  = (const float*)d_in[13];
    const float* cW1 = (const float*)d_in[14];
    const float* cb1 = (const float*)d_in[15];
    const float* cW2 = (const float*)d_in[16];
    const float* cb2 = (const float*)d_in[17];
    float* out = (float*)d_out;

    int M = in_sizes[0] / HDIM;     // 100000
    int E = in_sizes[1] / 2;        // 1600000
    const int* src = ei;
    const int* dst = ei + E;

    void *pA, *pAH, *pAL, *pW1H, *pW1L, *pW2H, *pW2L, *pCWH, *pCWL;
    void *ps1, *pt1, *ps2, *pt2;
    cudaGetSymbolAddress(&pA, g_bufA);
    cudaGetSymbolAddress(&pAH, g_actH);
    cudaGetSymbolAddress(&pAL, g_actL);
    cudaGetSymbolAddress(&pW1H, g_w1H);  cudaGetSymbolAddress(&pW1L, g_w1L);
    cudaGetSymbolAddress(&pW2H, g_w2H);  cudaGetSymbolAddress(&pW2L, g_w2L);
    cudaGetSymbolAddress(&pCWH, g_cwH);  cudaGetSymbolAddress(&pCWL, g_cwL);
    cudaGetSymbolAddress(&ps1, g_s1);
    cudaGetSymbolAddress(&pt1, g_t1);
    cudaGetSymbolAddress(&ps2, g_s2);
    cudaGetSymbolAddress(&pt2, g_t2);
    float* bufA = (float*)pA;
    __nv_bfloat16* actH = (__nv_bfloat16*)pAH;
    __nv_bfloat16* actL = (__nv_bfloat16*)pAL;

    const int SMEM = 4 * 128 * KS * (int)sizeof(__nv_bfloat16);  // 139264 B
    cudaFuncSetAttribute(k_mma128, cudaFuncAttributeMaxDynamicSharedMemorySize, SMEM);

    int nThreads = 256;
    int gNodes   = (M + nThreads - 1) / nThreads;
    int gEdges   = (E + nThreads - 1) / nThreads;
    int gGemm    = (M + 127) / 128;
    int gWarp    = (M + 7) / 8;
    int gScan    = (M + 1023) / 1024;
    int n4       = M * (HDIM / 4);
    int gCvt     = (n4 + nThreads - 1) / nThreads;

    // one-time conversions
    k_cvt<<<gCvt, nThreads>>>((const float4*)x, (__nv_bfloat162*)actH,
                              (__nv_bfloat162*)actL, n4);
    k_cvtW3<<<192, 256>>>(W1, W2, cW1,
                          (__nv_bfloat16*)pW1H, (__nv_bfloat16*)pW1L,
                          (__nv_bfloat16*)pW2H, (__nv_bfloat16*)pW2L,
                          (__nv_bfloat16*)pCWH, (__nv_bfloat16*)pCWL);

    // degree / CSR / normalization (built once, reused for both layers)
    k_zero_cnt<<<gNodes, nThreads>>>(M);
    k_count<<<gEdges, nThreads>>>(dst, E);
    k_dinv<<<gNodes, nThreads>>>(M);
    k_scan1<<<gScan, 1024>>>(M);
    k_scan2<<<1, 128>>>(gScan, M);
    k_scan3<<<gScan, 1024>>>(M);
    k_fill<<<gEdges, nThreads>>>(src, dst, E);
    k_prep<<<1, 256>>>(b1, gg1, be1, m1, v1, b2, gg2, be2, m2, v2);

    // layer 1: hw = x@W1 -> bufA; gather+BN+ReLU -> act hi/lo
    k_mma128<<<gGemm, 256, SMEM>>>(actH, actL, (__nv_bfloat16*)pW1H, (__nv_bfloat16*)pW1L,
                                   bufA, nullptr, nullptr, nullptr, M, 0);
    k_gather_bn<<<gWarp, 256>>>((const float4*)bufA, (__nv_bfloat162*)actH,
                                (__nv_bfloat162*)actL,
                                (const float*)ps1, (const float*)pt1, M);

    // layer 2
    k_mma128<<<gGemm, 256, SMEM>>>(actH, actL, (__nv_bfloat16*)pW2H, (__nv_bfloat16*)pW2L,
                                   bufA, nullptr, nullptr, nullptr, M, 0);
    k_gather_bn<<<gWarp, 256>>>((const float4*)bufA, (__nv_bfloat162*)actH,
                                (__nv_bfloat162*)actL,
                                (const float*)ps2, (const float*)pt2, M);

    // classifier fully fused: out = relu(act@cW1 + cb1) @ cW2 + cb2
    k_mma128<<<gGemm, 256, SMEM>>>(actH, actL, (__nv_bfloat16*)pCWH, (__nv_bfloat16*)pCWL,
                                   out, cb1, cW2, cb2, M, 1);
}

// round 15
// speedup vs baseline: 1.0574x; 1.0055x over previous
#include <cuda_runtime.h>
#include <cuda_bf16.h>
#include <cstdint>

#define NODES_MAX 100000
#define EDGES_MAX 1600000
#define HDIM 128
#define BN_EPS 1e-5f
#define SCAN_BLOCKS ((NODES_MAX + 1023) / 1024)   // 98
#define KS 136   // padded smem row stride in bf16 (272B = 16B-aligned, 4-bank shift/row)

// ---------------- scratch (static device globals; no allocation) ----------------
__device__ __align__(256) float g_bufA[(size_t)NODES_MAX * HDIM];            // hw (fp32)
__device__ __align__(256) __nv_bfloat16 g_actH[(size_t)NODES_MAX * HDIM];    // activation hi
__device__ __align__(256) __nv_bfloat16 g_actL[(size_t)NODES_MAX * HDIM];    // activation lo
__device__ __align__(256) __nv_bfloat16 g_w1H[HDIM * HDIM], g_w1L[HDIM * HDIM];  // W^T hi/lo
__device__ __align__(256) __nv_bfloat16 g_w2H[HDIM * HDIM], g_w2L[HDIM * HDIM];
__device__ __align__(256) __nv_bfloat16 g_cwH[HDIM * HDIM], g_cwL[HDIM * HDIM];
__device__ float g_dinv[NODES_MAX];
__device__ int   g_cnt[NODES_MAX];
__device__ int   g_incl[NODES_MAX];
__device__ int   g_blk[SCAN_BLOCKS];
__device__ int   g_rowptr[NODES_MAX + 1];
__device__ int   g_wpos[NODES_MAX];
__device__ __align__(256) float2 g_edge[EDGES_MAX];   // packed (src-as-float-bits, dinv[src])
__device__ float g_s1[HDIM], g_t1[HDIM], g_s2[HDIM], g_t2[HDIM];

// ---------------- degree count (int4-vectorized) ----------------
__global__ void k_count(const int* __restrict__ dst, int E) {
    int t = blockIdx.x * blockDim.x + threadIdx.x;
    int base = t * 4;
    if (base + 3 < E) {
        int4 d = *(const int4*)(dst + base);
        atomicAdd(&g_cnt[d.x], 1);
        atomicAdd(&g_cnt[d.y], 1);
        atomicAdd(&g_cnt[d.z], 1);
        atomicAdd(&g_cnt[d.w], 1);
    } else {
        for (int e = base; e < E; e++) atomicAdd(&g_cnt[dst[e]], 1);
    }
}

// ---------------- 3-pass parallel exclusive scan of degrees (+dinv fused) --------
__global__ __launch_bounds__(1024) void k_scan1(int n) {
    __shared__ int sh[1024];
    int t = threadIdx.x;
    int i = blockIdx.x * 1024 + t;
    int v = (i < n) ? g_cnt[i] : 0;
    if (i < n) g_dinv[i] = rsqrtf((float)v + 1.0f);  // fused: +1 self loop
    sh[t] = v;
    __syncthreads();
    #pragma unroll
    for (int off = 1; off < 1024; off <<= 1) {
        int u = (t >= off) ? sh[t - off] : 0;
        __syncthreads();
        sh[t] += u;
        __syncthreads();
    }
    if (i < n) g_incl[i] = sh[t];
    if (t == 1023) g_blk[blockIdx.x] = sh[1023];
}

__global__ __launch_bounds__(128) void k_scan2(int nb, int n) {
    __shared__ int sh[128];
    int t = threadIdx.x;
    int v = (t < nb) ? g_blk[t] : 0;
    sh[t] = v;
    __syncthreads();
    #pragma unroll
    for (int off = 1; off < 128; off <<= 1) {
        int u = (t >= off) ? sh[t - off] : 0;
        __syncthreads();
        sh[t] += u;
        __syncthreads();
    }
    if (t < nb) g_blk[t] = sh[t] - v;
    if (t == nb - 1) g_rowptr[n] = sh[t];
}

__global__ __launch_bounds__(1024) void k_scan3(int n) {
    int i = blockIdx.x * 1024 + threadIdx.x;
    if (i < n) {
        int e = g_blk[blockIdx.x] + g_incl[i] - g_cnt[i];
        g_rowptr[i] = e;
        g_wpos[i] = e;
    }
}

// ---------------- CSR fill: packed (src, dinv[src]) records ----------------
__global__ void k_fill(const int* __restrict__ src, const int* __restrict__ dst, int E) {
    int e = blockIdx.x * blockDim.x + threadIdx.x;
    if (e < E) {
        int s = src[e];
        int p = atomicAdd(&g_wpos[dst[e]], 1);
        float2 rec;
        rec.x = __int_as_float(s);
        rec.y = g_dinv[s];
        g_edge[p] = rec;
    }
}

// ---------------- one-time conversions ----------------
// x -> bf16 hi/lo  (fused: also zero g_cnt)
__global__ void k_cvt(const float4* __restrict__ in,
                      __nv_bfloat162* __restrict__ oh, __nv_bfloat162* __restrict__ ol,
                      int n4, int n) {
    int i = blockIdx.x * blockDim.x + threadIdx.x;
    if (i < n) g_cnt[i] = 0;          // fused degree-count zeroing
    if (i >= n4) return;
    float4 v = in[i];
    __nv_bfloat16 hx = __float2bfloat16(v.x), hy = __float2bfloat16(v.y);
    __nv_bfloat16 hz = __float2bfloat16(v.z), hw = __float2bfloat16(v.w);
    __nv_bfloat162 h01; h01.x = hx; h01.y = hy;
    __nv_bfloat162 h23; h23.x = hz; h23.y = hw;
    __nv_bfloat162 l01, l23;
    l01.x = __float2bfloat16(v.x - __bfloat162float(hx));
    l01.y = __float2bfloat16(v.y - __bfloat162float(hy));
    l23.x = __float2bfloat16(v.z - __bfloat162float(hz));
    l23.y = __float2bfloat16(v.w - __bfloat162float(hw));
    oh[i * 2] = h01; oh[i * 2 + 1] = h23;
    ol[i * 2] = l01; ol[i * 2 + 1] = l23;
}

// three W [k][n] fp32 -> W^T [n][k] bf16 hi/lo + BN prep, one launch (193 blocks)
__global__ void k_cvtW3(const float* __restrict__ W1, const float* __restrict__ W2,
                        const float* __restrict__ W3,
                        __nv_bfloat16* __restrict__ o1H, __nv_bfloat16* __restrict__ o1L,
                        __nv_bfloat16* __restrict__ o2H, __nv_bfloat16* __restrict__ o2L,
                        __nv_bfloat16* __restrict__ o3H, __nv_bfloat16* __restrict__ o3L,
                        const float* __restrict__ b1, const float* __restrict__ gg1,
                        const float* __restrict__ be1, const float* __restrict__ m1,
                        const float* __restrict__ v1,
                        const float* __restrict__ b2, const float* __restrict__ gg2,
                        const float* __restrict__ be2, const float* __restrict__ m2,
                        const float* __restrict__ v2) {
    int which = blockIdx.x >> 6;                  // 64 blocks per matrix; block 192 = prep
    if (which == 3) {
        int i = threadIdx.x;
        if (i < HDIM) {
            float s = gg1[i] * rsqrtf(v1[i] + BN_EPS);
            g_s1[i] = s;
            g_t1[i] = be1[i] + s * (b1[i] - m1[i]);
        } else {
            int j = i - HDIM;
            float s = gg2[j] * rsqrtf(v2[j] + BN_EPS);
            g_s2[j] = s;
            g_t2[j] = be2[j] + s * (b2[j] - m2[j]);
        }
        return;
    }
    int i = (blockIdx.x & 63) * 256 + threadIdx.x;  // 0..16383
    const float* W = (which == 0) ? W1 : (which == 1) ? W2 : W3;
    __nv_bfloat16* oh = (which == 0) ? o1H : (which == 1) ? o2H : o3H;
    __nv_bfloat16* ol = (which == 0) ? o1L : (which == 1) ? o2L : o3L;
    int k = i >> 7, n = i & 127;
    float v = W[i];
    __nv_bfloat16 h = __float2bfloat16(v);
    oh[n * HDIM + k] = h;
    ol[n * HDIM + k] = __float2bfloat16(v - __bfloat162float(h));
}

// ---------------- tensor-core GEMM: out[M,128] = A[M,128] @ W[128,128] ----------------
// 128-row tiles, 256 threads (8 warps, 16 rows x 128 cols per warp).
// acc = Ah*Bh + Ah*Bl + Al*Bh (fp32 accumulate).
// mode 0: plain fp32 store.  mode 1: out[r] = relu(acc+bias).cW2 + cb2 (fused head).
#define MMA16816(d, a, bl, bh)                                              \
    asm volatile(                                                           \
        "mma.sync.aligned.m16n8k16.row.col.f32.bf16.bf16.f32 "              \
        "{%0,%1,%2,%3}, {%4,%5,%6,%7}, {%8,%9}, {%0,%1,%2,%3};"             \
        : "+f"(d[0]), "+f"(d[1]), "+f"(d[2]), "+f"(d[3])                    \
        : "r"(a[0]), "r"(a[1]), "r"(a[2]), "r"(a[3]), "r"(bl), "r"(bh))

__global__ __launch_bounds__(256) void k_mma128(
    const __nv_bfloat16* __restrict__ AH, const __nv_bfloat16* __restrict__ AL,
    const __nv_bfloat16* __restrict__ WH, const __nv_bfloat16* __restrict__ WL,
    float* __restrict__ out, const float* __restrict__ bias,
    const float* __restrict__ cw2, const float* __restrict__ cb2,
    int M, int mode)
{
    extern __shared__ __align__(16) char smraw[];
    __nv_bfloat16* A0 = (__nv_bfloat16*)smraw;          // A hi  [128][KS]
    __nv_bfloat16* A1 = A0 + 128 * KS;                  // A lo
    __nv_bfloat16* B0 = A1 + 128 * KS;                  // W^T hi [n][KS]
    __nv_bfloat16* B1 = B0 + 128 * KS;                  // W^T lo

    int tid = threadIdx.x;
    int m0 = blockIdx.x * 128;

    // ---- stage A (pure copy): 2 threads per row, 64 k (128B = 8 float4) each ----
    {
        int r = tid >> 1, kh = (tid & 1) * 64;
        int m = m0 + r;
        float4* d0 = (float4*)(A0 + r * KS + kh);
        float4* d1 = (float4*)(A1 + r * KS + kh);
        if (m < M) {
            const float4* s0 = (const float4*)(AH + (size_t)m * HDIM + kh);
            const float4* s1 = (const float4*)(AL + (size_t)m * HDIM + kh);
            #pragma unroll
            for (int i = 0; i < 8; i++) { d0[i] = s0[i]; d1[i] = s1[i]; }
        } else {
            float4 z = {0.f, 0.f, 0.f, 0.f};
            #pragma unroll
            for (int i = 0; i < 8; i++) { d0[i] = z; d1[i] = z; }
        }
    }
    // ---- stage W^T (pure copy): 2048 float4 per buffer ----
    #pragma unroll
    for (int i = tid; i < 2048; i += 256) {
        int n = i >> 4, kc = i & 15;
        *(float4*)(B0 + n * KS + kc * 8) = ((const float4*)WH)[i];
        *(float4*)(B1 + n * KS + kc * 8) = ((const float4*)WL)[i];
    }
    __syncthreads();

    int lane = tid & 31, warp = tid >> 5;
    int gid = lane >> 2, tig = lane & 3;
    int rbase = warp * 16 + gid;            // local row for c0/c1; +8 for c2/c3

    float acc[16][4];
    #pragma unroll
    for (int nt = 0; nt < 16; nt++)
        #pragma unroll
        for (int j = 0; j < 4; j++) acc[nt][j] = 0.f;

    const __nv_bfloat16* a0r = A0 + rbase * KS + tig * 2;
    const __nv_bfloat16* a1r = A1 + rbase * KS + tig * 2;

    #pragma unroll
    for (int ks = 0; ks < 128; ks += 16) {
        uint32_t ah[4], al[4];
        ah[0] = *(const uint32_t*)(a0r + ks);
        ah[1] = *(const uint32_t*)(a0r + 8 * KS + ks);
        ah[2] = *(const uint32_t*)(a0r + ks + 8);
        ah[3] = *(const uint32_t*)(a0r + 8 * KS + ks + 8);
        al[0] = *(const uint32_t*)(a1r + ks);
        al[1] = *(const uint32_t*)(a1r + 8 * KS + ks);
        al[2] = *(const uint32_t*)(a1r + ks + 8);
        al[3] = *(const uint32_t*)(a1r + 8 * KS + ks + 8);
        #pragma unroll
        for (int nt = 0; nt < 16; nt++) {
            int col = nt * 8 + gid;
            const __nv_bfloat16* bh = B0 + col * KS + tig * 2;
            const __nv_bfloat16* bl = B1 + col * KS + tig * 2;
            uint32_t bh0 = *(const uint32_t*)(bh + ks);
            uint32_t bh1 = *(const uint32_t*)(bh + ks + 8);
            uint32_t bl0 = *(const uint32_t*)(bl + ks);
            uint32_t bl1 = *(const uint32_t*)(bl + ks + 8);
            MMA16816(acc[nt], ah, bh0, bh1);
            MMA16816(acc[nt], ah, bl0, bl1);
            MMA16816(acc[nt], al, bh0, bh1);
        }
    }

    int r1 = m0 + rbase, r2 = r1 + 8;
    if (mode == 0) {
        #pragma unroll
        for (int nt = 0; nt < 16; nt++) {
            int c = nt * 8 + tig * 2;
            if (r1 < M) {
                float2 v = {acc[nt][0], acc[nt][1]};
                *(float2*)(out + (size_t)r1 * HDIM + c) = v;
            }
            if (r2 < M) {
                float2 v = {acc[nt][2], acc[nt][3]};
                *(float2*)(out + (size_t)r2 * HDIM + c) = v;
            }
        }
    } else {
        float p1 = 0.f, p2 = 0.f;
        #pragma unroll
        for (int nt = 0; nt < 16; nt++) {
            int c = nt * 8 + tig * 2;
            float b0 = bias[c], b1v = bias[c + 1];
            float w0 = cw2[c], w1 = cw2[c + 1];
            p1 = fmaf(fmaxf(acc[nt][0] + b0, 0.f), w0, p1);
            p1 = fmaf(fmaxf(acc[nt][1] + b1v, 0.f), w1, p1);
            p2 = fmaf(fmaxf(acc[nt][2] + b0, 0.f), w0, p2);
            p2 = fmaf(fmaxf(acc[nt][3] + b1v, 0.f), w1, p2);
        }
        p1 += __shfl_xor_sync(0xFFFFFFFFu, p1, 1);
        p1 += __shfl_xor_sync(0xFFFFFFFFu, p1, 2);
        p2 += __shfl_xor_sync(0xFFFFFFFFu, p2, 1);
        p2 += __shfl_xor_sync(0xFFFFFFFFu, p2, 2);
        if (tig == 0) {
            float cb = cb2[0];
            if (r1 < M) out[r1] = p1 + cb;
            if (r2 < M) out[r2] = p2 + cb;
        }
    }
}

// ---------------- CSR gather + self-loop + BN + ReLU -> bf16 hi/lo ----------------
// packed edge records: (src, dinv[src]) — no random dinv load in the hot loop
__global__ __launch_bounds__(256) void k_gather_bn(
    const float4* __restrict__ hw,
    __nv_bfloat162* __restrict__ outH, __nv_bfloat162* __restrict__ outL,
    const float* __restrict__ sc, const float* __restrict__ tc, int n)
{
    int node = (blockIdx.x * blockDim.x + threadIdx.x) >> 5;
    if (node >= n) return;
    int lane = threadIdx.x & 31;

    int beg = g_rowptr[node];
    int end = g_rowptr[node + 1];
    float dd = g_dinv[node];

    float4 v = hw[(size_t)node * 32 + lane];
    float4 acc = {v.x * dd, v.y * dd, v.z * dd, v.w * dd};   // self loop

    int j = beg;
    for (; j + 1 < end; j += 2) {
        float2 e0 = g_edge[j], e1 = g_edge[j + 1];
        int s0 = __float_as_int(e0.x), s1 = __float_as_int(e1.x);
        float w0 = e0.y, w1 = e1.y;
        float4 h0 = hw[(size_t)s0 * 32 + lane];
        float4 h1 = hw[(size_t)s1 * 32 + lane];
        acc.x = fmaf(h0.x, w0, acc.x); acc.y = fmaf(h0.y, w0, acc.y);
        acc.z = fmaf(h0.z, w0, acc.z); acc.w = fmaf(h0.w, w0, acc.w);
        acc.x = fmaf(h1.x, w1, acc.x); acc.y = fmaf(h1.y, w1, acc.y);
        acc.z = fmaf(h1.z, w1, acc.z); acc.w = fmaf(h1.w, w1, acc.w);
    }
    if (j < end) {
        float2 e0 = g_edge[j];
        int s0 = __float_as_int(e0.x);
        float w0 = e0.y;
        float4 h0 = hw[(size_t)s0 * 32 + lane];
        acc.x = fmaf(h0.x, w0, acc.x); acc.y = fmaf(h0.y, w0, acc.y);
        acc.z = fmaf(h0.z, w0, acc.z); acc.w = fmaf(h0.w, w0, acc.w);
    }

    int c = lane << 2;
    float rx = fmaxf(fmaf(acc.x * dd, sc[c + 0], tc[c + 0]), 0.f);
    float ry = fmaxf(fmaf(acc.y * dd, sc[c + 1], tc[c + 1]), 0.f);
    float rz = fmaxf(fmaf(acc.z * dd, sc[c + 2], tc[c + 2]), 0.f);
    float rw = fmaxf(fmaf(acc.w * dd, sc[c + 3], tc[c + 3]), 0.f);

    __nv_bfloat16 hx = __float2bfloat16(rx), hy = __float2bfloat16(ry);
    __nv_bfloat16 hz = __float2bfloat16(rz), hw2 = __float2bfloat16(rw);
    __nv_bfloat162 h01; h01.x = hx; h01.y = hy;
    __nv_bfloat162 h23; h23.x = hz; h23.y = hw2;
    __nv_bfloat162 l01, l23;
    l01.x = __float2bfloat16(rx - __bfloat162float(hx));
    l01.y = __float2bfloat16(ry - __bfloat162float(hy));
    l23.x = __float2bfloat16(rz - __bfloat162float(hz));
    l23.y = __float2bfloat16(rw - __bfloat162float(hw2));

    size_t o = (size_t)node * 64 + lane * 2;
    outH[o] = h01; outH[o + 1] = h23;
    outL[o] = l01; outL[o + 1] = l23;
}

// ---------------- host orchestration ----------------
extern "C" void kernel_launch(void* const* d_in, const int* in_sizes, int n_in,
                              void* d_out, int out_size) {
    const float* x   = (const float*)d_in[0];
    const int*   ei  = (const int*)d_in[1];       // JAX x64-disabled: int32
    const float* W1  = (const float*)d_in[2];
    const float* b1  = (const float*)d_in[3];
    const float* gg1 = (const float*)d_in[4];
    const float* be1 = (const float*)d_in[5];
    const float* m1  = (const float*)d_in[6];
    const float* v1  = (const float*)d_in[7];
    const float* W2  = (const float*)d_in[8];
    const float* b2  = (const float*)d_in[9];
    const float* gg2 = (const float*)d_in[10];
    const float* be2 = (const float*)d_in[11];
    const float* m2  = (const float*)d_in[12];
    const float* v2  = (const float*)d_in[13];
    const float* cW1 = (const float*)d_in[14];
    const float* cb1 = (const float*)d_in[15];
    const float* cW2 = (const float*)d_in[16];
    const float* cb2 = (const float*)d_in[17];
    float* out = (float*)d_out;

    int M = in_sizes[0] / HDIM;     // 100000
    int E = in_sizes[1] / 2;        // 1600000
    const int* src = ei;
    const int* dst = ei + E;

    void *pA, *pAH, *pAL, *pW1H, *pW1L, *pW2H, *pW2L, *pCWH, *pCWL;
    void *ps1, *pt1, *ps2, *pt2;
    cudaGetSymbolAddress(&pA, g_bufA);
    cudaGetSymbolAddress(&pAH, g_actH);
    cudaGetSymbolAddress(&pAL, g_actL);
    cudaGetSymbolAddress(&pW1H, g_w1H);  cudaGetSymbolAddress(&pW1L, g_w1L);
    cudaGetSymbolAddress(&pW2H, g_w2H);  cudaGetSymbolAddress(&pW2L, g_w2L);
    cudaGetSymbolAddress(&pCWH, g_cwH);  cudaGetSymbolAddress(&pCWL, g_cwL);
    cudaGetSymbolAddress(&ps1, g_s1);
    cudaGetSymbolAddress(&pt1, g_t1);
    cudaGetSymbolAddress(&ps2, g_s2);
    cudaGetSymbolAddress(&pt2, g_t2);
    float* bufA = (float*)pA;
    __nv_bfloat16* actH = (__nv_bfloat16*)pAH;
    __nv_bfloat16* actL = (__nv_bfloat16*)pAL;

    const int SMEM = 4 * 128 * KS * (int)sizeof(__nv_bfloat16);  // 139264 B
    cudaFuncSetAttribute(k_mma128, cudaFuncAttributeMaxDynamicSharedMemorySize, SMEM);

    int nThreads = 256;
    int gEdges   = (E + nThreads - 1) / nThreads;
    int gCount   = (E / 4 + nThreads - 1) / nThreads;
    int gGemm    = (M + 127) / 128;
    int gWarp    = (M + 7) / 8;
    int gScan    = (M + 1023) / 1024;
    int n4       = M * (HDIM / 4);
    int gCvt     = (n4 + nThreads - 1) / nThreads;

    // conversions + fused degree-zero / BN-prep
    k_cvt<<<gCvt, nThreads>>>((const float4*)x, (__nv_bfloat162*)actH,
                              (__nv_bfloat162*)actL, n4, M);
    k_cvtW3<<<193, 256>>>(W1, W2, cW1,
                          (__nv_bfloat16*)pW1H, (__nv_bfloat16*)pW1L,
                          (__nv_bfloat16*)pW2H, (__nv_bfloat16*)pW2L,
                          (__nv_bfloat16*)pCWH, (__nv_bfloat16*)pCWL,
                          b1, gg1, be1, m1, v1, b2, gg2, be2, m2, v2);

    // degree / CSR (dinv fused into scan1; packed edge records)
    k_count<<<gCount, nThreads>>>(dst, E);
    k_scan1<<<gScan, 1024>>>(M);
    k_scan2<<<1, 128>>>(gScan, M);
    k_scan3<<<gScan, 1024>>>(M);
    k_fill<<<gEdges, nThreads>>>(src, dst, E);

    // layer 1: hw = x@W1 -> bufA; gather+BN+ReLU -> act hi/lo
    k_mma128<<<gGemm, 256, SMEM>>>(actH, actL, (__nv_bfloat16*)pW1H, (__nv_bfloat16*)pW1L,
                                   bufA, nullptr, nullptr, nullptr, M, 0);
    k_gather_bn<<<gWarp, 256>>>((const float4*)bufA, (__nv_bfloat162*)actH,
                                (__nv_bfloat162*)actL,
                                (const float*)ps1, (const float*)pt1, M);

    // layer 2
    k_mma128<<<gGemm, 256, SMEM>>>(actH, actL, (__nv_bfloat16*)pW2H, (__nv_bfloat16*)pW2L,
                                   bufA, nullptr, nullptr, nullptr, M, 0);
    k_gather_bn<<<gWarp, 256>>>((const float4*)bufA, (__nv_bfloat162*)actH,
                                (__nv_bfloat162*)actL,
                                (const float*)ps2, (const float*)pt2, M);

    // classifier fully fused: out = relu(act@cW1 + cb1) @ cW2 + cb2
    k_mma128<<<gGemm, 256, SMEM>>>(actH, actL, (__nv_bfloat16*)pCWH, (__nv_bfloat16*)pCWL,
                                   out, cb1, cW2, cb2, M, 1);
}

// round 16
// speedup vs baseline: 1.0906x; 1.0314x over previous
#include <cuda_runtime.h>
#include <cuda_bf16.h>
#include <cstdint>

#define NODES_MAX 100000
#define EDGES_MAX 1600000
#define HDIM 128
#define BN_EPS 1e-5f
#define SCAN_BLOCKS ((NODES_MAX + 1023) / 1024)   // 98
#define KS 136   // padded smem row stride in bf16 (272B = 16B-aligned, 4-bank shift/row)

// ---------------- scratch (static device globals; no allocation) ----------------
__device__ __align__(256) float g_bufA[(size_t)NODES_MAX * HDIM];            // hw (fp32)
__device__ __align__(256) __nv_bfloat16 g_actH[(size_t)NODES_MAX * HDIM];    // activation hi
__device__ __align__(256) __nv_bfloat16 g_actL[(size_t)NODES_MAX * HDIM];    // activation lo
__device__ __align__(256) __nv_bfloat16 g_w1H[HDIM * HDIM], g_w1L[HDIM * HDIM];  // W^T hi/lo
__device__ __align__(256) __nv_bfloat16 g_w2H[HDIM * HDIM], g_w2L[HDIM * HDIM];
__device__ __align__(256) __nv_bfloat16 g_cwH[HDIM * HDIM], g_cwL[HDIM * HDIM];
__device__ float g_dinv[NODES_MAX];
__device__ int   g_cnt[NODES_MAX];
__device__ int   g_incl[NODES_MAX];
__device__ int   g_blk[SCAN_BLOCKS];
__device__ int   g_rowptr[NODES_MAX + 1];
__device__ int   g_wpos[NODES_MAX];
__device__ __align__(256) float2 g_edge[EDGES_MAX];   // packed (src-as-float-bits, dinv[src])
__device__ float g_s1[HDIM], g_t1[HDIM], g_s2[HDIM], g_t2[HDIM];

// ---------------- degree zero + count ----------------
__global__ void k_zero_cnt(int n) {
    int i = blockIdx.x * blockDim.x + threadIdx.x;
    if (i < n) g_cnt[i] = 0;
}

__global__ void k_count(const int* __restrict__ dst, int E) {
    int t = blockIdx.x * blockDim.x + threadIdx.x;
    int base = t * 4;
    if (base + 3 < E) {
        int4 d = *(const int4*)(dst + base);
        atomicAdd(&g_cnt[d.x], 1);
        atomicAdd(&g_cnt[d.y], 1);
        atomicAdd(&g_cnt[d.z], 1);
        atomicAdd(&g_cnt[d.w], 1);
    } else {
        for (int e = base; e < E; e++) atomicAdd(&g_cnt[dst[e]], 1);
    }
}

// ---------------- 3-pass parallel exclusive scan of degrees (+dinv fused) --------
__global__ __launch_bounds__(1024) void k_scan1(int n) {
    __shared__ int sh[1024];
    int t = threadIdx.x;
    int i = blockIdx.x * 1024 + t;
    int v = (i < n) ? g_cnt[i] : 0;
    if (i < n) g_dinv[i] = rsqrtf((float)v + 1.0f);  // fused: +1 self loop
    sh[t] = v;
    __syncthreads();
    #pragma unroll
    for (int off = 1; off < 1024; off <<= 1) {
        int u = (t >= off) ? sh[t - off] : 0;
        __syncthreads();
        sh[t] += u;
        __syncthreads();
    }
    if (i < n) g_incl[i] = sh[t];
    if (t == 1023) g_blk[blockIdx.x] = sh[1023];
}

__global__ __launch_bounds__(128) void k_scan2(int nb, int n) {
    __shared__ int sh[128];
    int t = threadIdx.x;
    int v = (t < nb) ? g_blk[t] : 0;
    sh[t] = v;
    __syncthreads();
    #pragma unroll
    for (int off = 1; off < 128; off <<= 1) {
        int u = (t >= off) ? sh[t - off] : 0;
        __syncthreads();
        sh[t] += u;
        __syncthreads();
    }
    if (t < nb) g_blk[t] = sh[t] - v;
    if (t == nb - 1) g_rowptr[n] = sh[t];
}

__global__ __launch_bounds__(1024) void k_scan3(int n) {
    int i = blockIdx.x * 1024 + threadIdx.x;
    if (i < n) {
        int e = g_blk[blockIdx.x] + g_incl[i] - g_cnt[i];
        g_rowptr[i] = e;
        g_wpos[i] = e;
    }
}

// ---------------- CSR fill: packed (src, dinv[src]) records ----------------
__global__ void k_fill(const int* __restrict__ src, const int* __restrict__ dst, int E) {
    int e = blockIdx.x * blockDim.x + threadIdx.x;
    if (e < E) {
        int s = src[e];
        int p = atomicAdd(&g_wpos[dst[e]], 1);
        float2 rec;
        rec.x = __int_as_float(s);
        rec.y = g_dinv[s];
        g_edge[p] = rec;
    }
}

// ---------------- one-time conversions ----------------
// x -> bf16 hi/lo (row-major, same layout)
__global__ void k_cvt(const float4* __restrict__ in,
                      __nv_bfloat162* __restrict__ oh, __nv_bfloat162* __restrict__ ol,
                      int n4) {
    int i = blockIdx.x * blockDim.x + threadIdx.x;
    if (i >= n4) return;
    float4 v = in[i];
    __nv_bfloat16 hx = __float2bfloat16(v.x), hy = __float2bfloat16(v.y);
    __nv_bfloat16 hz = __float2bfloat16(v.z), hw = __float2bfloat16(v.w);
    __nv_bfloat162 h01; h01.x = hx; h01.y = hy;
    __nv_bfloat162 h23; h23.x = hz; h23.y = hw;
    __nv_bfloat162 l01, l23;
    l01.x = __float2bfloat16(v.x - __bfloat162float(hx));
    l01.y = __float2bfloat16(v.y - __bfloat162float(hy));
    l23.x = __float2bfloat16(v.z - __bfloat162float(hz));
    l23.y = __float2bfloat16(v.w - __bfloat162float(hw));
    oh[i * 2] = h01; oh[i * 2 + 1] = h23;
    ol[i * 2] = l01; ol[i * 2 + 1] = l23;
}

// three W [k][n] fp32 -> W^T [n][k] bf16 hi/lo + BN prep, one launch (193 blocks)
__global__ void k_cvtW3(const float* __restrict__ W1, const float* __restrict__ W2,
                        const float* __restrict__ W3,
                        __nv_bfloat16* __restrict__ o1H, __nv_bfloat16* __restrict__ o1L,
                        __nv_bfloat16* __restrict__ o2H, __nv_bfloat16* __restrict__ o2L,
                        __nv_bfloat16* __restrict__ o3H, __nv_bfloat16* __restrict__ o3L,
                        const float* __restrict__ b1, const float* __restrict__ gg1,
                        const float* __restrict__ be1, const float* __restrict__ m1,
                        const float* __restrict__ v1,
                        const float* __restrict__ b2, const float* __restrict__ gg2,
                        const float* __restrict__ be2, const float* __restrict__ m2,
                        const float* __restrict__ v2) {
    int which = blockIdx.x >> 6;                  // 64 blocks per matrix; block 192 = prep
    if (which == 3) {
        int i = threadIdx.x;
        if (i < HDIM) {
            float s = gg1[i] * rsqrtf(v1[i] + BN_EPS);
            g_s1[i] = s;
            g_t1[i] = be1[i] + s * (b1[i] - m1[i]);
        } else {
            int j = i - HDIM;
            float s = gg2[j] * rsqrtf(v2[j] + BN_EPS);
            g_s2[j] = s;
            g_t2[j] = be2[j] + s * (b2[j] - m2[j]);
        }
        return;
    }
    int i = (blockIdx.x & 63) * 256 + threadIdx.x;  // 0..16383
    const float* W = (which == 0) ? W1 : (which == 1) ? W2 : W3;
    __nv_bfloat16* oh = (which == 0) ? o1H : (which == 1) ? o2H : o3H;
    __nv_bfloat16* ol = (which == 0) ? o1L : (which == 1) ? o2L : o3L;
    int k = i >> 7, n = i & 127;
    float v = W[i];
    __nv_bfloat16 h = __float2bfloat16(v);
    oh[n * HDIM + k] = h;
    ol[n * HDIM + k] = __float2bfloat16(v - __bfloat162float(h));
}

// ---------------- tensor-core GEMM: out[M,128] = A[M,128] @ W[128,128] ----------------
// 128-row tiles, 256 threads (8 warps, 16 rows x 128 cols per warp).
// acc = Ah*Bh + Ah*Bl + Al*Bh (fp32 accumulate).
// mode 0: plain fp32 store.  mode 1: out[r] = relu(acc+bias).cW2 + cb2 (fused head).
#define MMA16816(d, a, bl, bh)                                              \
    asm volatile(                                                           \
        "mma.sync.aligned.m16n8k16.row.col.f32.bf16.bf16.f32 "              \
        "{%0,%1,%2,%3}, {%4,%5,%6,%7}, {%8,%9}, {%0,%1,%2,%3};"             \
        : "+f"(d[0]), "+f"(d[1]), "+f"(d[2]), "+f"(d[3])                    \
        : "r"(a[0]), "r"(a[1]), "r"(a[2]), "r"(a[3]), "r"(bl), "r"(bh))

__global__ __launch_bounds__(256) void k_mma128(
    const __nv_bfloat16* __restrict__ AH, const __nv_bfloat16* __restrict__ AL,
    const __nv_bfloat16* __restrict__ WH, const __nv_bfloat16* __restrict__ WL,
    float* __restrict__ out, const float* __restrict__ bias,
    const float* __restrict__ cw2, const float* __restrict__ cb2,
    int M, int mode)
{
    extern __shared__ __align__(16) char smraw[];
    __nv_bfloat16* A0 = (__nv_bfloat16*)smraw;          // A hi  [128][KS]
    __nv_bfloat16* A1 = A0 + 128 * KS;                  // A lo
    __nv_bfloat16* B0 = A1 + 128 * KS;                  // W^T hi [n][KS]
    __nv_bfloat16* B1 = B0 + 128 * KS;                  // W^T lo

    int tid = threadIdx.x;
    int m0 = blockIdx.x * 128;

    // ---- stage A (pure copy): 2 threads per row, 64 k (128B = 8 float4) each ----
    {
        int r = tid >> 1, kh = (tid & 1) * 64;
        int m = m0 + r;
        float4* d0 = (float4*)(A0 + r * KS + kh);
        float4* d1 = (float4*)(A1 + r * KS + kh);
        if (m < M) {
            const float4* s0 = (const float4*)(AH + (size_t)m * HDIM + kh);
            const float4* s1 = (const float4*)(AL + (size_t)m * HDIM + kh);
            #pragma unroll
            for (int i = 0; i < 8; i++) { d0[i] = s0[i]; d1[i] = s1[i]; }
        } else {
            float4 z = {0.f, 0.f, 0.f, 0.f};
            #pragma unroll
            for (int i = 0; i < 8; i++) { d0[i] = z; d1[i] = z; }
        }
    }
    // ---- stage W^T (pure copy): 2048 float4 per buffer ----
    #pragma unroll
    for (int i = tid; i < 2048; i += 256) {
        int n = i >> 4, kc = i & 15;
        *(float4*)(B0 + n * KS + kc * 8) = ((const float4*)WH)[i];
        *(float4*)(B1 + n * KS + kc * 8) = ((const float4*)WL)[i];
    }
    __syncthreads();

    int lane = tid & 31, warp = tid >> 5;
    int gid = lane >> 2, tig = lane & 3;
    int rbase = warp * 16 + gid;            // local row for c0/c1; +8 for c2/c3

    float acc[16][4];
    #pragma unroll
    for (int nt = 0; nt < 16; nt++)
        #pragma unroll
        for (int j = 0; j < 4; j++) acc[nt][j] = 0.f;

    const __nv_bfloat16* a0r = A0 + rbase * KS + tig * 2;
    const __nv_bfloat16* a1r = A1 + rbase * KS + tig * 2;

    #pragma unroll
    for (int ks = 0; ks < 128; ks += 16) {
        uint32_t ah[4], al[4];
        ah[0] = *(const uint32_t*)(a0r + ks);
        ah[1] = *(const uint32_t*)(a0r + 8 * KS + ks);
        ah[2] = *(const uint32_t*)(a0r + ks + 8);
        ah[3] = *(const uint32_t*)(a0r + 8 * KS + ks + 8);
        al[0] = *(const uint32_t*)(a1r + ks);
        al[1] = *(const uint32_t*)(a1r + 8 * KS + ks);
        al[2] = *(const uint32_t*)(a1r + ks + 8);
        al[3] = *(const uint32_t*)(a1r + 8 * KS + ks + 8);
        #pragma unroll
        for (int nt = 0; nt < 16; nt++) {
            int col = nt * 8 + gid;
            const __nv_bfloat16* bh = B0 + col * KS + tig * 2;
            const __nv_bfloat16* bl = B1 + col * KS + tig * 2;
            uint32_t bh0 = *(const uint32_t*)(bh + ks);
            uint32_t bh1 = *(const uint32_t*)(bh + ks + 8);
            uint32_t bl0 = *(const uint32_t*)(bl + ks);
            uint32_t bl1 = *(const uint32_t*)(bl + ks + 8);
            MMA16816(acc[nt], ah, bh0, bh1);
            MMA16816(acc[nt], ah, bl0, bl1);
            MMA16816(acc[nt], al, bh0, bh1);
        }
    }

    int r1 = m0 + rbase, r2 = r1 + 8;
    if (mode == 0) {
        #pragma unroll
        for (int nt = 0; nt < 16; nt++) {
            int c = nt * 8 + tig * 2;
            if (r1 < M) {
                float2 v = {acc[nt][0], acc[nt][1]};
                *(float2*)(out + (size_t)r1 * HDIM + c) = v;
            }
            if (r2 < M) {
                float2 v = {acc[nt][2], acc[nt][3]};
                *(float2*)(out + (size_t)r2 * HDIM + c) = v;
            }
        }
    } else {
        float p1 = 0.f, p2 = 0.f;
        #pragma unroll
        for (int nt = 0; nt < 16; nt++) {
            int c = nt * 8 + tig * 2;
            float b0 = bias[c], b1v = bias[c + 1];
            float w0 = cw2[c], w1 = cw2[c + 1];
            p1 = fmaf(fmaxf(acc[nt][0] + b0, 0.f), w0, p1);
            p1 = fmaf(fmaxf(acc[nt][1] + b1v, 0.f), w1, p1);
            p2 = fmaf(fmaxf(acc[nt][2] + b0, 0.f), w0, p2);
            p2 = fmaf(fmaxf(acc[nt][3] + b1v, 0.f), w1, p2);
        }
        p1 += __shfl_xor_sync(0xFFFFFFFFu, p1, 1);
        p1 += __shfl_xor_sync(0xFFFFFFFFu, p1, 2);
        p2 += __shfl_xor_sync(0xFFFFFFFFu, p2, 1);
        p2 += __shfl_xor_sync(0xFFFFFFFFu, p2, 2);
        if (tig == 0) {
            float cb = cb2[0];
            if (r1 < M) out[r1] = p1 + cb;
            if (r2 < M) out[r2] = p2 + cb;
        }
    }
}

// ---------------- CSR gather + self-loop + BN + ReLU -> bf16 hi/lo ----------------
__global__ __launch_bounds__(256) void k_gather_bn(
    const float4* __restrict__ hw,
    __nv_bfloat162* __restrict__ outH, __nv_bfloat162* __restrict__ outL,
    const float* __restrict__ sc, const float* __restrict__ tc, int n)
{
    int node = (blockIdx.x * blockDim.x + threadIdx.x) >> 5;
    if (node >= n) return;
    int lane = threadIdx.x & 31;

    int beg = g_rowptr[node];
    int end = g_rowptr[node + 1];
    float dd = g_dinv[node];

    float4 v = hw[(size_t)node * 32 + lane];
    float4 acc = {v.x * dd, v.y * dd, v.z * dd, v.w * dd};   // self loop

    int j = beg;
    for (; j + 1 < end; j += 2) {
        float2 e0 = g_edge[j], e1 = g_edge[j + 1];
        int s0 = __float_as_int(e0.x), s1 = __float_as_int(e1.x);
        float w0 = e0.y, w1 = e1.y;
        float4 h0 = hw[(size_t)s0 * 32 + lane];
        float4 h1 = hw[(size_t)s1 * 32 + lane];
        acc.x = fmaf(h0.x, w0, acc.x); acc.y = fmaf(h0.y, w0, acc.y);
        acc.z = fmaf(h0.z, w0, acc.z); acc.w = fmaf(h0.w, w0, acc.w);
        acc.x = fmaf(h1.x, w1, acc.x); acc.y = fmaf(h1.y, w1, acc.y);
        acc.z = fmaf(h1.z, w1, acc.z); acc.w = fmaf(h1.w, w1, acc.w);
    }
    if (j < end) {
        float2 e0 = g_edge[j];
        int s0 = __float_as_int(e0.x);
        float w0 = e0.y;
        float4 h0 = hw[(size_t)s0 * 32 + lane];
        acc.x = fmaf(h0.x, w0, acc.x); acc.y = fmaf(h0.y, w0, acc.y);
        acc.z = fmaf(h0.z, w0, acc.z); acc.w = fmaf(h0.w, w0, acc.w);
    }

    int c = lane << 2;
    float rx = fmaxf(fmaf(acc.x * dd, sc[c + 0], tc[c + 0]), 0.f);
    float ry = fmaxf(fmaf(acc.y * dd, sc[c + 1], tc[c + 1]), 0.f);
    float rz = fmaxf(fmaf(acc.z * dd, sc[c + 2], tc[c + 2]), 0.f);
    float rw = fmaxf(fmaf(acc.w * dd, sc[c + 3], tc[c + 3]), 0.f);

    __nv_bfloat16 hx = __float2bfloat16(rx), hy = __float2bfloat16(ry);
    __nv_bfloat16 hz = __float2bfloat16(rz), hw2 = __float2bfloat16(rw);
    __nv_bfloat162 h01; h01.x = hx; h01.y = hy;
    __nv_bfloat162 h23; h23.x = hz; h23.y = hw2;
    __nv_bfloat162 l01, l23;
    l01.x = __float2bfloat16(rx - __bfloat162float(hx));
    l01.y = __float2bfloat16(ry - __bfloat162float(hy));
    l23.x = __float2bfloat16(rz - __bfloat162float(hz));
    l23.y = __float2bfloat16(rw - __bfloat162float(hw2));

    size_t o = (size_t)node * 64 + lane * 2;
    outH[o] = h01; outH[o + 1] = h23;
    outL[o] = l01; outL[o + 1] = l23;
}

// ---------------- host orchestration ----------------
extern "C" void kernel_launch(void* const* d_in, const int* in_sizes, int n_in,
                              void* d_out, int out_size) {
    const float* x   = (const float*)d_in[0];
    const int*   ei  = (const int*)d_in[1];       // JAX x64-disabled: int32
    const float* W1  = (const float*)d_in[2];
    const float* b1  = (const float*)d_in[3];
    const float* gg1 = (const float*)d_in[4];
    const float* be1 = (const float*)d_in[5];
    const float* m1  = (const float*)d_in[6];
    const float* v1  = (const float*)d_in[7];
    const float* W2  = (const float*)d_in[8];
    const float* b2  = (const float*)d_in[9];
    const float* gg2 = (const float*)d_in[10];
    const float* be2 = (const float*)d_in[11];
    const float* m2  = (const float*)d_in[12];
    const float* v2  = (const float*)d_in[13];
    const float* cW1 = (const float*)d_in[14];
    const float* cb1 = (const float*)d_in[15];
    const float* cW2 = (const float*)d_in[16];
    const float* cb2 = (const float*)d_in[17];
    float* out = (float*)d_out;

    int M = in_sizes[0] / HDIM;     // 100000
    int E = in_sizes[1] / 2;        // 1600000
    const int* src = ei;
    const int* dst = ei + E;

    void *pA, *pAH, *pAL, *pW1H, *pW1L, *pW2H, *pW2L, *pCWH, *pCWL;
    void *ps1, *pt1, *ps2, *pt2;
    cudaGetSymbolAddress(&pA, g_bufA);
    cudaGetSymbolAddress(&pAH, g_actH);
    cudaGetSymbolAddress(&pAL, g_actL);
    cudaGetSymbolAddress(&pW1H, g_w1H);  cudaGetSymbolAddress(&pW1L, g_w1L);
    cudaGetSymbolAddress(&pW2H, g_w2H);  cudaGetSymbolAddress(&pW2L, g_w2L);
    cudaGetSymbolAddress(&pCWH, g_cwH);  cudaGetSymbolAddress(&pCWL, g_cwL);
    cudaGetSymbolAddress(&ps1, g_s1);
    cudaGetSymbolAddress(&pt1, g_t1);
    cudaGetSymbolAddress(&ps2, g_s2);
    cudaGetSymbolAddress(&pt2, g_t2);
    float* bufA = (float*)pA;
    __nv_bfloat16* actH = (__nv_bfloat16*)pAH;
    __nv_bfloat16* actL = (__nv_bfloat16*)pAL;

    const int SMEM = 4 * 128 * KS * (int)sizeof(__nv_bfloat16);  // 139264 B
    cudaFuncSetAttribute(k_mma128, cudaFuncAttributeMaxDynamicSharedMemorySize, SMEM);

    int nThreads = 256;
    int gNodes   = (M + nThreads - 1) / nThreads;
    int gEdges   = (E + nThreads - 1) / nThreads;
    int gCount   = (E / 4 + nThreads - 1) / nThreads;
    int gGemm    = (M + 127) / 128;
    int gWarp    = (M + 7) / 8;
    int gScan    = (M + 1023) / 1024;
    int n4       = M * (HDIM / 4);
    int gCvt     = (n4 + nThreads - 1) / nThreads;

    // fork a worker stream for the CSR build (runs concurrently with cvt + GEMM1)
    cudaStream_t s2;
    cudaStreamCreateWithFlags(&s2, cudaStreamNonBlocking);
    cudaEvent_t evFork, evJoin;
    cudaEventCreateWithFlags(&evFork, cudaEventDisableTiming);
    cudaEventCreateWithFlags(&evJoin, cudaEventDisableTiming);

    cudaEventRecord(evFork, 0);
    cudaStreamWaitEvent(s2, evFork, 0);

    // ---- stream s2: CSR build (zero -> count -> scan -> fill) ----
    k_zero_cnt<<<gNodes, nThreads, 0, s2>>>(M);
    k_count<<<gCount, nThreads, 0, s2>>>(dst, E);
    k_scan1<<<gScan, 1024, 0, s2>>>(M);
    k_scan2<<<1, 128, 0, s2>>>(gScan, M);
    k_scan3<<<gScan, 1024, 0, s2>>>(M);
    k_fill<<<gEdges, nThreads, 0, s2>>>(src, dst, E);
    cudaEventRecord(evJoin, s2);

    // ---- stream 0: conversions + GEMM1 (independent of CSR) ----
    k_cvt<<<gCvt, nThreads>>>((const float4*)x, (__nv_bfloat162*)actH,
                              (__nv_bfloat162*)actL, n4);
    k_cvtW3<<<193, 256>>>(W1, W2, cW1,
                          (__nv_bfloat16*)pW1H, (__nv_bfloat16*)pW1L,
                          (__nv_bfloat16*)pW2H, (__nv_bfloat16*)pW2L,
                          (__nv_bfloat16*)pCWH, (__nv_bfloat16*)pCWL,
                          b1, gg1, be1, m1, v1, b2, gg2, be2, m2, v2);
    k_mma128<<<gGemm, 256, SMEM>>>(actH, actL, (__nv_bfloat16*)pW1H, (__nv_bfloat16*)pW1L,
                                   bufA, nullptr, nullptr, nullptr, M, 0);

    // join: gather needs CSR + GEMM1
    cudaStreamWaitEvent(0, evJoin, 0);

    k_gather_bn<<<gWarp, 256>>>((const float4*)bufA, (__nv_bfloat162*)actH,
                                (__nv_bfloat162*)actL,
                                (const float*)ps1, (const float*)pt1, M);

    // layer 2
    k_mma128<<<gGemm, 256, SMEM>>>(actH, actL, (__nv_bfloat16*)pW2H, (__nv_bfloat16*)pW2L,
                                   bufA, nullptr, nullptr, nullptr, M, 0);
    k_gather_bn<<<gWarp, 256>>>((const float4*)bufA, (__nv_bfloat162*)actH,
                                (__nv_bfloat162*)actL,
                                (const float*)ps2, (const float*)pt2, M);

    // classifier fully fused: out = relu(act@cW1 + cb1) @ cW2 + cb2
    k_mma128<<<gGemm, 256, SMEM>>>(actH, actL, (__nv_bfloat16*)pCWH, (__nv_bfloat16*)pCWL,
                                   out, cb1, cW2, cb2, M, 1);

    cudaEventDestroy(evFork);
    cudaEventDestroy(evJoin);
    cudaStreamDestroy(s2);
}

// round 17
// speedup vs baseline: 1.1070x; 1.0150x over previous
#include <cuda_runtime.h>
#include <cuda_bf16.h>
#include <cstdint>

#define NODES_MAX 100000
#define EDGES_MAX 1600000
#define HDIM 128
#define BN_EPS 1e-5f
#define SCAN_BLOCKS ((NODES_MAX + 1023) / 1024)   // 98
#define KS 136   // padded smem row stride in bf16 (272B = 16B-aligned, 4-bank shift/row)

// ---------------- scratch (static device globals; no allocation) ----------------
__device__ __align__(256) float g_bufA[(size_t)NODES_MAX * HDIM];            // ping
__device__ __align__(256) float g_bufB[(size_t)NODES_MAX * HDIM];            // pong
__device__ __align__(256) __nv_bfloat16 g_w1H[HDIM * HDIM], g_w1L[HDIM * HDIM];  // W^T hi/lo
__device__ __align__(256) __nv_bfloat16 g_w2H[HDIM * HDIM], g_w2L[HDIM * HDIM];
__device__ __align__(256) __nv_bfloat16 g_cwH[HDIM * HDIM], g_cwL[HDIM * HDIM];
__device__ float g_dinv[NODES_MAX];
__device__ int   g_cnt[NODES_MAX];
__device__ int   g_incl[NODES_MAX];
__device__ int   g_blk[SCAN_BLOCKS];
__device__ int   g_rowptr[NODES_MAX + 1];
__device__ int   g_wpos[NODES_MAX];
__device__ __align__(256) float2 g_edge[EDGES_MAX];   // packed (src-as-float-bits, dinv[src])
__device__ float g_s1[HDIM], g_t1[HDIM], g_s2[HDIM], g_t2[HDIM];

// ---------------- degree zero + count ----------------
__global__ void k_zero_cnt(int n) {
    int i = blockIdx.x * blockDim.x + threadIdx.x;
    if (i < n) g_cnt[i] = 0;
}

__global__ void k_count(const int* __restrict__ dst, int E) {
    int t = blockIdx.x * blockDim.x + threadIdx.x;
    int base = t * 4;
    if (base + 3 < E) {
        int4 d = *(const int4*)(dst + base);
        atomicAdd(&g_cnt[d.x], 1);
        atomicAdd(&g_cnt[d.y], 1);
        atomicAdd(&g_cnt[d.z], 1);
        atomicAdd(&g_cnt[d.w], 1);
    } else {
        for (int e = base; e < E; e++) atomicAdd(&g_cnt[dst[e]], 1);
    }
}

// ---------------- 3-pass parallel exclusive scan of degrees (+dinv fused) --------
__global__ __launch_bounds__(1024) void k_scan1(int n) {
    __shared__ int sh[1024];
    int t = threadIdx.x;
    int i = blockIdx.x * 1024 + t;
    int v = (i < n) ? g_cnt[i] : 0;
    if (i < n) g_dinv[i] = rsqrtf((float)v + 1.0f);  // fused: +1 self loop
    sh[t] = v;
    __syncthreads();
    #pragma unroll
    for (int off = 1; off < 1024; off <<= 1) {
        int u = (t >= off) ? sh[t - off] : 0;
        __syncthreads();
        sh[t] += u;
        __syncthreads();
    }
    if (i < n) g_incl[i] = sh[t];
    if (t == 1023) g_blk[blockIdx.x] = sh[1023];
}

__global__ __launch_bounds__(128) void k_scan2(int nb, int n) {
    __shared__ int sh[128];
    int t = threadIdx.x;
    int v = (t < nb) ? g_blk[t] : 0;
    sh[t] = v;
    __syncthreads();
    #pragma unroll
    for (int off = 1; off < 128; off <<= 1) {
        int u = (t >= off) ? sh[t - off] : 0;
        __syncthreads();
        sh[t] += u;
        __syncthreads();
    }
    if (t < nb) g_blk[t] = sh[t] - v;
    if (t == nb - 1) g_rowptr[n] = sh[t];
}

__global__ __launch_bounds__(1024) void k_scan3(int n) {
    int i = blockIdx.x * 1024 + threadIdx.x;
    if (i < n) {
        int e = g_blk[blockIdx.x] + g_incl[i] - g_cnt[i];
        g_rowptr[i] = e;
        g_wpos[i] = e;
    }
}

// ---------------- CSR fill: packed (src, dinv[src]) records ----------------
__global__ void k_fill(const int* __restrict__ src, const int* __restrict__ dst, int E) {
    int e = blockIdx.x * blockDim.x + threadIdx.x;
    if (e < E) {
        int s = src[e];
        int p = atomicAdd(&g_wpos[dst[e]], 1);
        float2 rec;
        rec.x = __int_as_float(s);
        rec.y = g_dinv[s];
        g_edge[p] = rec;
    }
}

// ---------------- weights: three W [k][n] fp32 -> W^T [n][k] bf16 hi/lo + BN prep ----
__global__ void k_cvtW3(const float* __restrict__ W1, const float* __restrict__ W2,
                        const float* __restrict__ W3,
                        __nv_bfloat16* __restrict__ o1H, __nv_bfloat16* __restrict__ o1L,
                        __nv_bfloat16* __restrict__ o2H, __nv_bfloat16* __restrict__ o2L,
                        __nv_bfloat16* __restrict__ o3H, __nv_bfloat16* __restrict__ o3L,
                        const float* __restrict__ b1, const float* __restrict__ gg1,
                        const float* __restrict__ be1, const float* __restrict__ m1,
                        const float* __restrict__ v1,
                        const float* __restrict__ b2, const float* __restrict__ gg2,
                        const float* __restrict__ be2, const float* __restrict__ m2,
                        const float* __restrict__ v2) {
    int which = blockIdx.x >> 6;                  // 64 blocks per matrix; block 192 = prep
    if (which == 3) {
        int i = threadIdx.x;
        if (i < HDIM) {
            float s = gg1[i] * rsqrtf(v1[i] + BN_EPS);
            g_s1[i] = s;
            g_t1[i] = be1[i] + s * (b1[i] - m1[i]);
        } else {
            int j = i - HDIM;
            float s = gg2[j] * rsqrtf(v2[j] + BN_EPS);
            g_s2[j] = s;
            g_t2[j] = be2[j] + s * (b2[j] - m2[j]);
        }
        return;
    }
    int i = (blockIdx.x & 63) * 256 + threadIdx.x;  // 0..16383
    const float* W = (which == 0) ? W1 : (which == 1) ? W2 : W3;
    __nv_bfloat16* oh = (which == 0) ? o1H : (which == 1) ? o2H : o3H;
    __nv_bfloat16* ol = (which == 0) ? o1L : (which == 1) ? o2L : o3L;
    int k = i >> 7, n = i & 127;
    float v = W[i];
    __nv_bfloat16 h = __float2bfloat16(v);
    oh[n * HDIM + k] = h;
    ol[n * HDIM + k] = __float2bfloat16(v - __bfloat162float(h));
}

// ---------------- tensor-core GEMM: out[M,128] = A[M,128] @ W[128,128] ----------------
// A is fp32; hi/lo split happens inline during staging (once per element — no
// global hi/lo round-trip). 128-row tiles, 256 threads.
// acc = Ah*Bh + Ah*Bl + Al*Bh (fp32 accumulate).
// mode 0: plain fp32 store.  mode 1: out[r] = relu(acc+bias).cW2 + cb2 (fused head).
#define MMA16816(d, a, bl, bh)                                              \
    asm volatile(                                                           \
        "mma.sync.aligned.m16n8k16.row.col.f32.bf16.bf16.f32 "              \
        "{%0,%1,%2,%3}, {%4,%5,%6,%7}, {%8,%9}, {%0,%1,%2,%3};"             \
        : "+f"(d[0]), "+f"(d[1]), "+f"(d[2]), "+f"(d[3])                    \
        : "r"(a[0]), "r"(a[1]), "r"(a[2]), "r"(a[3]), "r"(bl), "r"(bh))

__global__ __launch_bounds__(256) void k_mma128(
    const float* __restrict__ A,
    const __nv_bfloat16* __restrict__ WH, const __nv_bfloat16* __restrict__ WL,
    float* __restrict__ out, const float* __restrict__ bias,
    const float* __restrict__ cw2, const float* __restrict__ cb2,
    int M, int mode)
{
    extern __shared__ __align__(16) char smraw[];
    __nv_bfloat16* A0 = (__nv_bfloat16*)smraw;          // A hi  [128][KS]
    __nv_bfloat16* A1 = A0 + 128 * KS;                  // A lo
    __nv_bfloat16* B0 = A1 + 128 * KS;                  // W^T hi [n][KS]
    __nv_bfloat16* B1 = B0 + 128 * KS;                  // W^T lo

    int tid = threadIdx.x;
    int m0 = blockIdx.x * 128;

    // ---- stage A with inline hi/lo split: 2 threads per row, 64 k each ----
    {
        int r = tid >> 1, kh = (tid & 1) * 64;
        int m = m0 + r;
        __nv_bfloat162* d0 = (__nv_bfloat162*)(A0 + r * KS + kh);
        __nv_bfloat162* d1 = (__nv_bfloat162*)(A1 + r * KS + kh);
        if (m < M) {
            const float4* s = (const float4*)(A + (size_t)m * HDIM + kh);
            #pragma unroll
            for (int i = 0; i < 16; i++) {
                float4 v = s[i];
                __nv_bfloat16 hx = __float2bfloat16(v.x), hy = __float2bfloat16(v.y);
                __nv_bfloat16 hz = __float2bfloat16(v.z), hw = __float2bfloat16(v.w);
                __nv_bfloat162 h01; h01.x = hx; h01.y = hy;
                __nv_bfloat162 h23; h23.x = hz; h23.y = hw;
                __nv_bfloat162 l01, l23;
                l01.x = __float2bfloat16(v.x - __bfloat162float(hx));
                l01.y = __float2bfloat16(v.y - __bfloat162float(hy));
                l23.x = __float2bfloat16(v.z - __bfloat162float(hz));
                l23.y = __float2bfloat16(v.w - __bfloat162float(hw));
                d0[i * 2] = h01; d0[i * 2 + 1] = h23;
                d1[i * 2] = l01; d1[i * 2 + 1] = l23;
            }
        } else {
            __nv_bfloat162 z; z.x = __float2bfloat16(0.f); z.y = z.x;
            #pragma unroll
            for (int i = 0; i < 32; i++) { d0[i] = z; d1[i] = z; }
        }
    }
    // ---- stage W^T (pure copy): 2048 float4 per buffer ----
    #pragma unroll
    for (int i = tid; i < 2048; i += 256) {
        int n = i >> 4, kc = i & 15;
        *(float4*)(B0 + n * KS + kc * 8) = ((const float4*)WH)[i];
        *(float4*)(B1 + n * KS + kc * 8) = ((const float4*)WL)[i];
    }
    __syncthreads();

    int lane = tid & 31, warp = tid >> 5;
    int gid = lane >> 2, tig = lane & 3;
    int rbase = warp * 16 + gid;            // local row for c0/c1; +8 for c2/c3

    float acc[16][4];
    #pragma unroll
    for (int nt = 0; nt < 16; nt++)
        #pragma unroll
        for (int j = 0; j < 4; j++) acc[nt][j] = 0.f;

    const __nv_bfloat16* a0r = A0 + rbase * KS + tig * 2;
    const __nv_bfloat16* a1r = A1 + rbase * KS + tig * 2;

    #pragma unroll
    for (int ks = 0; ks < 128; ks += 16) {
        uint32_t ah[4], al[4];
        ah[0] = *(const uint32_t*)(a0r + ks);
        ah[1] = *(const uint32_t*)(a0r + 8 * KS + ks);
        ah[2] = *(const uint32_t*)(a0r + ks + 8);
        ah[3] = *(const uint32_t*)(a0r + 8 * KS + ks + 8);
        al[0] = *(const uint32_t*)(a1r + ks);
        al[1] = *(const uint32_t*)(a1r + 8 * KS + ks);
        al[2] = *(const uint32_t*)(a1r + ks + 8);
        al[3] = *(const uint32_t*)(a1r + 8 * KS + ks + 8);
        #pragma unroll
        for (int nt = 0; nt < 16; nt++) {
            int col = nt * 8 + gid;
            const __nv_bfloat16* bh = B0 + col * KS + tig * 2;
            const __nv_bfloat16* bl = B1 + col * KS + tig * 2;
            uint32_t bh0 = *(const uint32_t*)(bh + ks);
            uint32_t bh1 = *(const uint32_t*)(bh + ks + 8);
            uint32_t bl0 = *(const uint32_t*)(bl + ks);
            uint32_t bl1 = *(const uint32_t*)(bl + ks + 8);
            MMA16816(acc[nt], ah, bh0, bh1);
            MMA16816(acc[nt], ah, bl0, bl1);
            MMA16816(acc[nt], al, bh0, bh1);
        }
    }

    int r1 = m0 + rbase, r2 = r1 + 8;
    if (mode == 0) {
        #pragma unroll
        for (int nt = 0; nt < 16; nt++) {
            int c = nt * 8 + tig * 2;
            if (r1 < M) {
                float2 v = {acc[nt][0], acc[nt][1]};
                *(float2*)(out + (size_t)r1 * HDIM + c) = v;
            }
            if (r2 < M) {
                float2 v = {acc[nt][2], acc[nt][3]};
                *(float2*)(out + (size_t)r2 * HDIM + c) = v;
            }
        }
    } else {
        float p1 = 0.f, p2 = 0.f;
        #pragma unroll
        for (int nt = 0; nt < 16; nt++) {
            int c = nt * 8 + tig * 2;
            float b0 = bias[c], b1v = bias[c + 1];
            float w0 = cw2[c], w1 = cw2[c + 1];
            p1 = fmaf(fmaxf(acc[nt][0] + b0, 0.f), w0, p1);
            p1 = fmaf(fmaxf(acc[nt][1] + b1v, 0.f), w1, p1);
            p2 = fmaf(fmaxf(acc[nt][2] + b0, 0.f), w0, p2);
            p2 = fmaf(fmaxf(acc[nt][3] + b1v, 0.f), w1, p2);
        }
        p1 += __shfl_xor_sync(0xFFFFFFFFu, p1, 1);
        p1 += __shfl_xor_sync(0xFFFFFFFFu, p1, 2);
        p2 += __shfl_xor_sync(0xFFFFFFFFu, p2, 1);
        p2 += __shfl_xor_sync(0xFFFFFFFFu, p2, 2);
        if (tig == 0) {
            float cb = cb2[0];
            if (r1 < M) out[r1] = p1 + cb;
            if (r2 < M) out[r2] = p2 + cb;
        }
    }
}

// ---------------- CSR gather + self-loop + BN + ReLU -> fp32 ----------------
__global__ __launch_bounds__(256) void k_gather_bn(
    const float4* __restrict__ hw, float4* __restrict__ out,
    const float* __restrict__ sc, const float* __restrict__ tc, int n)
{
    int node = (blockIdx.x * blockDim.x + threadIdx.x) >> 5;
    if (node >= n) return;
    int lane = threadIdx.x & 31;

    int beg = g_rowptr[node];
    int end = g_rowptr[node + 1];
    float dd = g_dinv[node];

    float4 v = hw[(size_t)node * 32 + lane];
    float4 acc = {v.x * dd, v.y * dd, v.z * dd, v.w * dd};   // self loop

    int j = beg;
    for (; j + 1 < end; j += 2) {
        float2 e0 = g_edge[j], e1 = g_edge[j + 1];
        int s0 = __float_as_int(e0.x), s1 = __float_as_int(e1.x);
        float w0 = e0.y, w1 = e1.y;
        float4 h0 = hw[(size_t)s0 * 32 + lane];
        float4 h1 = hw[(size_t)s1 * 32 + lane];
        acc.x = fmaf(h0.x, w0, acc.x); acc.y = fmaf(h0.y, w0, acc.y);
        acc.z = fmaf(h0.z, w0, acc.z); acc.w = fmaf(h0.w, w0, acc.w);
        acc.x = fmaf(h1.x, w1, acc.x); acc.y = fmaf(h1.y, w1, acc.y);
        acc.z = fmaf(h1.z, w1, acc.z); acc.w = fmaf(h1.w, w1, acc.w);
    }
    if (j < end) {
        float2 e0 = g_edge[j];
        int s0 = __float_as_int(e0.x);
        float w0 = e0.y;
        float4 h0 = hw[(size_t)s0 * 32 + lane];
        acc.x = fmaf(h0.x, w0, acc.x); acc.y = fmaf(h0.y, w0, acc.y);
        acc.z = fmaf(h0.z, w0, acc.z); acc.w = fmaf(h0.w, w0, acc.w);
    }

    int c = lane << 2;
    float4 r;
    r.x = fmaxf(fmaf(acc.x * dd, sc[c + 0], tc[c + 0]), 0.f);
    r.y = fmaxf(fmaf(acc.y * dd, sc[c + 1], tc[c + 1]), 0.f);
    r.z = fmaxf(fmaf(acc.z * dd, sc[c + 2], tc[c + 2]), 0.f);
    r.w = fmaxf(fmaf(acc.w * dd, sc[c + 3], tc[c + 3]), 0.f);
    out[(size_t)node * 32 + lane] = r;
}

// ---------------- host orchestration ----------------
extern "C" void kernel_launch(void* const* d_in, const int* in_sizes, int n_in,
                              void* d_out, int out_size) {
    const float* x   = (const float*)d_in[0];
    const int*   ei  = (const int*)d_in[1];       // JAX x64-disabled: int32
    const float* W1  = (const float*)d_in[2];
    const float* b1  = (const float*)d_in[3];
    const float* gg1 = (const float*)d_in[4];
    const float* be1 = (const float*)d_in[5];
    const float* m1  = (const float*)d_in[6];
    const float* v1  = (const float*)d_in[7];
    const float* W2  = (const float*)d_in[8];
    const float* b2  = (const float*)d_in[9];
    const float* gg2 = (const float*)d_in[10];
    const float* be2 = (const float*)d_in[11];
    const float* m2  = (const float*)d_in[12];
    const float* v2  = (const float*)d_in[13];
    const float* cW1 = (const float*)d_in[14];
    const float* cb1 = (const float*)d_in[15];
    const float* cW2 = (const float*)d_in[16];
    const float* cb2 = (const float*)d_in[17];
    float* out = (float*)d_out;

    int M = in_sizes[0] / HDIM;     // 100000
    int E = in_sizes[1] / 2;        // 1600000
    const int* src = ei;
    const int* dst = ei + E;

    void *pA, *pB, *pW1H, *pW1L, *pW2H, *pW2L, *pCWH, *pCWL;
    void *ps1, *pt1, *ps2, *pt2;
    cudaGetSymbolAddress(&pA, g_bufA);
    cudaGetSymbolAddress(&pB, g_bufB);
    cudaGetSymbolAddress(&pW1H, g_w1H);  cudaGetSymbolAddress(&pW1L, g_w1L);
    cudaGetSymbolAddress(&pW2H, g_w2H);  cudaGetSymbolAddress(&pW2L, g_w2L);
    cudaGetSymbolAddress(&pCWH, g_cwH);  cudaGetSymbolAddress(&pCWL, g_cwL);
    cudaGetSymbolAddress(&ps1, g_s1);
    cudaGetSymbolAddress(&pt1, g_t1);
    cudaGetSymbolAddress(&ps2, g_s2);
    cudaGetSymbolAddress(&pt2, g_t2);
    float* bufA = (float*)pA;
    float* bufB = (float*)pB;

    const int SMEM = 4 * 128 * KS * (int)sizeof(__nv_bfloat16);  // 139264 B
    cudaFuncSetAttribute(k_mma128, cudaFuncAttributeMaxDynamicSharedMemorySize, SMEM);

    int nThreads = 256;
    int gNodes   = (M + nThreads - 1) / nThreads;
    int gEdges   = (E + nThreads - 1) / nThreads;
    int gCount   = (E / 4 + nThreads - 1) / nThreads;
    int gGemm    = (M + 127) / 128;
    int gWarp    = (M + 7) / 8;
    int gScan    = (M + 1023) / 1024;

    // fork a worker stream for the CSR build (runs concurrently with cvtW + GEMM1)
    cudaStream_t s2;
    cudaStreamCreateWithFlags(&s2, cudaStreamNonBlocking);
    cudaEvent_t evFork, evJoin;
    cudaEventCreateWithFlags(&evFork, cudaEventDisableTiming);
    cudaEventCreateWithFlags(&evJoin, cudaEventDisableTiming);

    cudaEventRecord(evFork, 0);
    cudaStreamWaitEvent(s2, evFork, 0);

    // ---- stream s2: CSR build (zero -> count -> scan -> fill) ----
    k_zero_cnt<<<gNodes, nThreads, 0, s2>>>(M);
    k_count<<<gCount, nThreads, 0, s2>>>(dst, E);
    k_scan1<<<gScan, 1024, 0, s2>>>(M);
    k_scan2<<<1, 128, 0, s2>>>(gScan, M);
    k_scan3<<<gScan, 1024, 0, s2>>>(M);
    k_fill<<<gEdges, nThreads, 0, s2>>>(src, dst, E);
    cudaEventRecord(evJoin, s2);

    // ---- stream 0: weight conversion + GEMM1 (A = x fp32, inline split) ----
    k_cvtW3<<<193, 256>>>(W1, W2, cW1,
                          (__nv_bfloat16*)pW1H, (__nv_bfloat16*)pW1L,
                          (__nv_bfloat16*)pW2H, (__nv_bfloat16*)pW2L,
                          (__nv_bfloat16*)pCWH, (__nv_bfloat16*)pCWL,
                          b1, gg1, be1, m1, v1, b2, gg2, be2, m2, v2);
    k_mma128<<<gGemm, 256, SMEM>>>(x, (__nv_bfloat16*)pW1H, (__nv_bfloat16*)pW1L,
                                   bufA, nullptr, nullptr, nullptr, M, 0);

    // join: gather needs CSR + GEMM1
    cudaStreamWaitEvent(0, evJoin, 0);

    // layer 1 aggregate: bufA (hw1) -> bufB (act1, fp32)
    k_gather_bn<<<gWarp, 256>>>((const float4*)bufA, (float4*)bufB,
                                (const float*)ps1, (const float*)pt1, M);

    // layer 2: bufB -> bufA (hw2); aggregate -> bufB (act2)
    k_mma128<<<gGemm, 256, SMEM>>>(bufB, (__nv_bfloat16*)pW2H, (__nv_bfloat16*)pW2L,
                                   bufA, nullptr, nullptr, nullptr, M, 0);
    k_gather_bn<<<gWarp, 256>>>((const float4*)bufA, (float4*)bufB,
                                (const float*)ps2, (const float*)pt2, M);

    // classifier fully fused: out = relu(bufB@cW1 + cb1) @ cW2 + cb2
    k_mma128<<<gGemm, 256, SMEM>>>(bufB, (__nv_bfloat16*)pCWH, (__nv_bfloat16*)pCWL,
                                   out, cb1, cW2, cb2, M, 1);

    cudaEventDestroy(evFork);
    cudaEventDestroy(evJoin);
    cudaStreamDestroy(s2);
}